// round 3
// baseline (speedup 1.0000x reference)
#include <cuda_runtime.h>
#include <cstdint>

// Problem constants
constexpr int Bb  = 4;
constexpr int Ss  = 2048;
constexpr int Dd  = 2048;
constexpr int Hh  = 16;
constexpr int DK  = 128;
constexpr int Mm  = Bb * Ss;          // 8192 rows

// ---------------------------------------------------------------------------
// Scratch (static __device__ arrays; runtime allocation is forbidden)
// ---------------------------------------------------------------------------
__device__ float g_qlin[(size_t)Mm * Dd];   // Q projection; later reused as attention output
__device__ float g_klin[(size_t)Mm * Dd];   // K projection
__device__ float g_vlin[(size_t)Mm * Dd];   // V projection (consumed directly by flash)
__device__ float g_qt  [(size_t)Bb * Hh * DK * Ss];  // roped Q, [B,H,DK,S]
__device__ float g_kt  [(size_t)Bb * Hh * DK * Ss];  // roped K, [B,H,DK,S]

// ---------------------------------------------------------------------------
// GEMM:  C[M,N] = A[M,K] * B[N,K]^T   (both row-major, "NT")
// 128x128 block tile, BK=16, 256 threads, 8x8 register tile per thread.
// ---------------------------------------------------------------------------
__global__ __launch_bounds__(256) void gemm_nt_kernel(
    const float* __restrict__ A, const float* __restrict__ B, float* __restrict__ C,
    int M, int N, int K)
{
    __shared__ __align__(16) float As[16][132];
    __shared__ __align__(16) float Bs[16][132];

    const int tid = threadIdx.x;
    const int tx  = tid & 15;
    const int ty  = tid >> 4;
    const int m0  = blockIdx.y * 128;
    const int n0  = blockIdx.x * 128;
    const int nk  = K >> 4;

    float acc[8][8];
#pragma unroll
    for (int i = 0; i < 8; i++)
#pragma unroll
        for (int j = 0; j < 8; j++) acc[i][j] = 0.f;

    // prologue: tile 0 -> smem (transposed to K-major)
#pragma unroll
    for (int i = 0; i < 2; i++) {
        int f   = tid + i * 256;
        int row = f >> 2;
        int kc  = (f & 3) << 2;
        float4 va = *(const float4*)&A[(size_t)(m0 + row) * K + kc];
        As[kc + 0][row] = va.x; As[kc + 1][row] = va.y;
        As[kc + 2][row] = va.z; As[kc + 3][row] = va.w;
        float4 vb = *(const float4*)&B[(size_t)(n0 + row) * K + kc];
        Bs[kc + 0][row] = vb.x; Bs[kc + 1][row] = vb.y;
        Bs[kc + 2][row] = vb.z; Bs[kc + 3][row] = vb.w;
    }
    __syncthreads();

    float4 pa[2], pb[2];
    for (int kt = 0; kt < nk; kt++) {
        const int knext = (kt + 1) << 4;
        if (kt + 1 < nk) {
#pragma unroll
            for (int i = 0; i < 2; i++) {
                int f   = tid + i * 256;
                int row = f >> 2;
                int kc  = (f & 3) << 2;
                pa[i] = *(const float4*)&A[(size_t)(m0 + row) * K + knext + kc];
                pb[i] = *(const float4*)&B[(size_t)(n0 + row) * K + knext + kc];
            }
        }
#pragma unroll
        for (int k = 0; k < 16; k++) {
            float4 a0 = *(float4*)&As[k][ty * 4];
            float4 a1 = *(float4*)&As[k][64 + ty * 4];
            float4 b0 = *(float4*)&Bs[k][tx * 4];
            float4 b1 = *(float4*)&Bs[k][64 + tx * 4];
            float ar[8] = {a0.x, a0.y, a0.z, a0.w, a1.x, a1.y, a1.z, a1.w};
            float br[8] = {b0.x, b0.y, b0.z, b0.w, b1.x, b1.y, b1.z, b1.w};
#pragma unroll
            for (int i = 0; i < 8; i++)
#pragma unroll
                for (int j = 0; j < 8; j++)
                    acc[i][j] = fmaf(ar[i], br[j], acc[i][j]);
        }
        __syncthreads();
        if (kt + 1 < nk) {
#pragma unroll
            for (int i = 0; i < 2; i++) {
                int f   = tid + i * 256;
                int row = f >> 2;
                int kc  = (f & 3) << 2;
                As[kc + 0][row] = pa[i].x; As[kc + 1][row] = pa[i].y;
                As[kc + 2][row] = pa[i].z; As[kc + 3][row] = pa[i].w;
                Bs[kc + 0][row] = pb[i].x; Bs[kc + 1][row] = pb[i].y;
                Bs[kc + 2][row] = pb[i].z; Bs[kc + 3][row] = pb[i].w;
            }
        }
        __syncthreads();
    }

#pragma unroll
    for (int i = 0; i < 8; i++) {
        int r = m0 + ((i < 4) ? (ty * 4 + i) : (64 + ty * 4 + i - 4));
        float4 c0 = make_float4(acc[i][0], acc[i][1], acc[i][2], acc[i][3]);
        float4 c1 = make_float4(acc[i][4], acc[i][5], acc[i][6], acc[i][7]);
        *(float4*)&C[(size_t)r * N + n0 + tx * 4]      = c0;
        *(float4*)&C[(size_t)r * N + n0 + 64 + tx * 4] = c1;
    }
}

// ---------------------------------------------------------------------------
// RoPE + transpose:  in [B,S,H*DK] -> out [B,H,DK,S]  (interleaved-pair RoPE)
// block = (s-tile of 32, h, b); 256 threads; smem tile for coalesced writes
// ---------------------------------------------------------------------------
__global__ __launch_bounds__(256) void rope_transpose_kernel(
    const float* __restrict__ in, const float* __restrict__ cosd,
    const float* __restrict__ sind, float* __restrict__ out)
{
    __shared__ float tile[128][33];
    const int b  = blockIdx.z;
    const int h  = blockIdx.y;
    const int s0 = blockIdx.x * 32;
    const int tid = threadIdx.x;

#pragma unroll
    for (int i = 0; i < 8; i++) {
        int item = tid + i * 256;     // 32 s * 64 pairs
        int sl = item >> 6;
        int j  = item & 63;
        int s  = s0 + sl;
        float2 xp = *(const float2*)&in[(size_t)(b * Ss + s) * Dd + h * DK + 2 * j];
        float c  = cosd[s * 64 + j];
        float sn = sind[s * 64 + j];
        tile[2 * j][sl]     = xp.x * c - xp.y * sn;
        tile[2 * j + 1][sl] = xp.y * c + xp.x * sn;
    }
    __syncthreads();
#pragma unroll
    for (int i = 0; i < 16; i++) {
        int item = tid + i * 256;     // 128 dk * 32 s
        int dk = item >> 5;
        int sl = item & 31;
        out[(size_t)((b * Hh + h) * DK + dk) * Ss + s0 + sl] = tile[dk][sl];
    }
}

// ---------------------------------------------------------------------------
// Flash attention (causal, online softmax), fp32.
// grid: (S/64, H, B); 256 threads (ty=tid/16, tx=tid&15)
// Score tile 64x64: thread owns 4 rows (4ty+i) x 4 cols (4tx+j).
// PV: out tile 64x128: thread owns 4 rows x 8 cols (8tx+j).
// Q,K staged K-major [128][68]; V row-major [64][132]; P [64][68].
// ---------------------------------------------------------------------------
constexpr int FL_Q  = 128 * 68;
constexpr int FL_K  = 128 * 68;
constexpr int FL_V  = 64 * 132;
constexpr int FL_P  = 64 * 68;
constexpr size_t FL_SMEM = (size_t)(FL_Q + FL_K + FL_V + FL_P) * sizeof(float);

__global__ __launch_bounds__(256) void flash_kernel(
    const float* __restrict__ qt, const float* __restrict__ kt,
    const float* __restrict__ v, float* __restrict__ o)
{
    extern __shared__ float sm[];
    float* Qs = sm;
    float* Ks = sm + FL_Q;
    float* Vs = Ks + FL_K;
    float* Ps = Vs + FL_V;

    const int qb = blockIdx.x;
    const int h  = blockIdx.y;
    const int b  = blockIdx.z;
    const int tid = threadIdx.x;
    const int tx = tid & 15;
    const int ty = tid >> 4;
    const float scale = 0.08838834764831845f;  // 1/sqrt(128)

    // Load Q tile [128 k][64 rows]
    const float* qbase = qt + (size_t)(b * Hh + h) * DK * Ss + qb * 64;
#pragma unroll
    for (int i = 0; i < 8; i++) {
        int f  = tid + i * 256;
        int k  = f >> 4;
        int rc = (f & 15) << 2;
        *(float4*)&Qs[k * 68 + rc] = *(const float4*)&qbase[(size_t)k * Ss + rc];
    }

    float m_i[4], l_i[4], accO[4][8];
#pragma unroll
    for (int i = 0; i < 4; i++) {
        m_i[i] = -1e30f; l_i[i] = 0.f;
#pragma unroll
        for (int j = 0; j < 8; j++) accO[i][j] = 0.f;
    }

    const float* kbase0 = kt + (size_t)(b * Hh + h) * DK * Ss;
    const float* vbase  = v + (size_t)b * Ss * Dd + h * DK;

    for (int kb = 0; kb <= qb; kb++) {
        __syncthreads();  // prior PV done (also covers Q-write visibility on iter 0)
        const float* kbase = kbase0 + kb * 64;
#pragma unroll
        for (int i = 0; i < 8; i++) {
            int f  = tid + i * 256;
            int k  = f >> 4;
            int rc = (f & 15) << 2;
            *(float4*)&Ks[k * 68 + rc] = *(const float4*)&kbase[(size_t)k * Ss + rc];
        }
#pragma unroll
        for (int i = 0; i < 8; i++) {
            int f  = tid + i * 256;
            int c  = f >> 5;
            int dc = (f & 31) << 2;
            *(float4*)&Vs[c * 132 + dc] =
                *(const float4*)&vbase[(size_t)(kb * 64 + c) * Dd + dc];
        }
        __syncthreads();

        // Scores: 64x64, each thread 4x4
        float sc[4][4];
#pragma unroll
        for (int i = 0; i < 4; i++)
#pragma unroll
            for (int j = 0; j < 4; j++) sc[i][j] = 0.f;

#pragma unroll 4
        for (int k = 0; k < 128; k++) {
            float4 a = *(float4*)&Qs[k * 68 + 4 * ty];
            float4 bq = *(float4*)&Ks[k * 68 + 4 * tx];
            float ar[4] = {a.x, a.y, a.z, a.w};
            float br[4] = {bq.x, bq.y, bq.z, bq.w};
#pragma unroll
            for (int i = 0; i < 4; i++)
#pragma unroll
                for (int j = 0; j < 4; j++)
                    sc[i][j] = fmaf(ar[i], br[j], sc[i][j]);
        }

        const bool diag = (kb == qb);
#pragma unroll
        for (int i = 0; i < 4; i++)
#pragma unroll
            for (int j = 0; j < 4; j++) {
                float s = sc[i][j] * scale;
                if (diag && (4 * tx + j > 4 * ty + i)) s = -1e30f;
                sc[i][j] = s;
            }

        // Online softmax per row (reduce across the 16 tx lanes)
#pragma unroll
        for (int i = 0; i < 4; i++) {
            float rm = fmaxf(fmaxf(sc[i][0], sc[i][1]), fmaxf(sc[i][2], sc[i][3]));
#pragma unroll
            for (int off = 8; off >= 1; off >>= 1)
                rm = fmaxf(rm, __shfl_xor_sync(0xffffffffu, rm, off));
            float mnew  = fmaxf(m_i[i], rm);
            float alpha = __expf(m_i[i] - mnew);
            float rs = 0.f;
#pragma unroll
            for (int j = 0; j < 4; j++) {
                float p = __expf(sc[i][j] - mnew);
                Ps[(4 * ty + i) * 68 + 4 * tx + j] = p;
                rs += p;
            }
#pragma unroll
            for (int off = 8; off >= 1; off >>= 1)
                rs += __shfl_xor_sync(0xffffffffu, rs, off);
            l_i[i] = l_i[i] * alpha + rs;
            m_i[i] = mnew;
#pragma unroll
            for (int j = 0; j < 8; j++) accO[i][j] *= alpha;
        }
        __syncthreads();

        // PV: out 64x128, each thread 4 rows x 8 cols
#pragma unroll 2
        for (int c = 0; c < 64; c++) {
            float4 v0 = *(float4*)&Vs[c * 132 + 8 * tx];
            float4 v1 = *(float4*)&Vs[c * 132 + 8 * tx + 4];
            float vr[8] = {v0.x, v0.y, v0.z, v0.w, v1.x, v1.y, v1.z, v1.w};
#pragma unroll
            for (int i = 0; i < 4; i++) {
                float p = Ps[(4 * ty + i) * 68 + c];
#pragma unroll
                for (int j = 0; j < 8; j++)
                    accO[i][j] = fmaf(p, vr[j], accO[i][j]);
            }
        }
    }

    // Epilogue: write [B,S,H*DK]
#pragma unroll
    for (int i = 0; i < 4; i++) {
        int row = qb * 64 + 4 * ty + i;
        float inv = 1.f / l_i[i];
        float4 o0 = make_float4(accO[i][0] * inv, accO[i][1] * inv,
                                accO[i][2] * inv, accO[i][3] * inv);
        float4 o1 = make_float4(accO[i][4] * inv, accO[i][5] * inv,
                                accO[i][6] * inv, accO[i][7] * inv);
        size_t base = (size_t)(b * Ss + row) * Dd + h * DK + 8 * tx;
        *(float4*)&o[base]     = o0;
        *(float4*)&o[base + 4] = o1;
    }
}

// ---------------------------------------------------------------------------
// Launch
// ---------------------------------------------------------------------------
extern "C" void kernel_launch(void* const* d_in, const int* in_sizes, int n_in,
                              void* d_out, int out_size)
{
    (void)in_sizes; (void)n_in; (void)out_size;
    const float* x    = (const float*)d_in[0];
    const float* Wq   = (const float*)d_in[1];
    const float* Wk   = (const float*)d_in[2];
    const float* Wv   = (const float*)d_in[3];
    const float* Wo   = (const float*)d_in[4];
    const float* cosd = (const float*)d_in[5];
    const float* sind = (const float*)d_in[6];
    float* out = (float*)d_out;

    float *qlin, *klin, *vlin, *qt, *ktp;
    cudaGetSymbolAddress((void**)&qlin, g_qlin);
    cudaGetSymbolAddress((void**)&klin, g_klin);
    cudaGetSymbolAddress((void**)&vlin, g_vlin);
    cudaGetSymbolAddress((void**)&qt,   g_qt);
    cudaGetSymbolAddress((void**)&ktp,  g_kt);

    cudaFuncSetAttribute(flash_kernel,
                         cudaFuncAttributeMaxDynamicSharedMemorySize, (int)FL_SMEM);

    dim3 ggrid(Dd / 128, Mm / 128);
    gemm_nt_kernel<<<ggrid, 256>>>(x, Wq, qlin, Mm, Dd, Dd);
    gemm_nt_kernel<<<ggrid, 256>>>(x, Wk, klin, Mm, Dd, Dd);
    gemm_nt_kernel<<<ggrid, 256>>>(x, Wv, vlin, Mm, Dd, Dd);

    dim3 rgrid(Ss / 32, Hh, Bb);
    rope_transpose_kernel<<<rgrid, 256>>>(qlin, cosd, sind, qt);
    rope_transpose_kernel<<<rgrid, 256>>>(klin, cosd, sind, ktp);

    dim3 fgrid(Ss / 64, Hh, Bb);
    flash_kernel<<<fgrid, 256, FL_SMEM>>>(qt, ktp, vlin, qlin /* reused as O */);

    gemm_nt_kernel<<<ggrid, 256>>>(qlin, Wo, out, Mm, Dd, Dd);
}

// round 5
// speedup vs baseline: 1.5127x; 1.5127x over previous
#include <cuda_runtime.h>
#include <cuda_bf16.h>
#include <cstdint>

// Problem constants
constexpr int Bb  = 4;
constexpr int Ss  = 2048;
constexpr int Dd  = 2048;
constexpr int Hh  = 16;
constexpr int DK  = 128;
constexpr int Mm  = Bb * Ss;          // 8192 rows

// ---------------------------------------------------------------------------
// Scratch (static __device__ arrays; runtime allocation is forbidden)
// ---------------------------------------------------------------------------
__device__ float g_qlin[(size_t)Mm * Dd];
__device__ float g_klin[(size_t)Mm * Dd];
__device__ float g_vlin[(size_t)Mm * Dd];
__device__ float g_qt  [(size_t)Bb * Hh * DK * Ss];  // roped Q, [B,H,DK,S]
__device__ float g_kt  [(size_t)Bb * Hh * DK * Ss];  // roped K, [B,H,DK,S]

// bf16 split buffers
__device__ __align__(256) __nv_bfloat16 g_xhi[(size_t)Mm * Dd];
__device__ __align__(256) __nv_bfloat16 g_xlo[(size_t)Mm * Dd];
__device__ __align__(256) __nv_bfloat16 g_whi[4][(size_t)Dd * Dd];
__device__ __align__(256) __nv_bfloat16 g_wlo[4][(size_t)Dd * Dd];

// ---------------------------------------------------------------------------
// Baseline-ISA helpers (valid on plain sm_100 target: sm_80-era PTX)
// ---------------------------------------------------------------------------
__device__ __forceinline__ uint32_t smem_u32(const void* p) {
    uint32_t a;
    asm("{ .reg .u64 t; cvta.to.shared.u64 t, %1; cvt.u32.u64 %0, t; }"
        : "=r"(a) : "l"(p));
    return a;
}
__device__ __forceinline__ void ldsm4(uint32_t* r, uint32_t addr) {
    asm volatile("ldmatrix.sync.aligned.m8n8.x4.shared.b16 {%0,%1,%2,%3}, [%4];"
                 : "=r"(r[0]), "=r"(r[1]), "=r"(r[2]), "=r"(r[3])
                 : "r"(addr));
}
__device__ __forceinline__ void mma16816(float* c, const uint32_t* a,
                                         const uint32_t* b) {
    asm volatile(
        "mma.sync.aligned.m16n8k16.row.col.f32.bf16.bf16.f32 "
        "{%0,%1,%2,%3}, {%4,%5,%6,%7}, {%8,%9}, {%0,%1,%2,%3};"
        : "+f"(c[0]), "+f"(c[1]), "+f"(c[2]), "+f"(c[3])
        : "r"(a[0]), "r"(a[1]), "r"(a[2]), "r"(a[3]), "r"(b[0]), "r"(b[1]));
}
#define CP_COMMIT() asm volatile("cp.async.commit_group;" ::: "memory")

// ---------------------------------------------------------------------------
// Split fp32 -> (bf16 hi, bf16 lo).  4 elements / thread.
// ---------------------------------------------------------------------------
__global__ __launch_bounds__(256) void split_kernel(
    const float* __restrict__ in, __nv_bfloat16* __restrict__ hi,
    __nv_bfloat16* __restrict__ lo, int n)
{
    int i = (blockIdx.x * 256 + threadIdx.x) * 4;
    if (i >= n) return;
    float4 v = *(const float4*)&in[i];
    __nv_bfloat16 h0 = __float2bfloat16(v.x);
    __nv_bfloat16 h1 = __float2bfloat16(v.y);
    __nv_bfloat16 h2 = __float2bfloat16(v.z);
    __nv_bfloat16 h3 = __float2bfloat16(v.w);
    __nv_bfloat16 l0 = __float2bfloat16(v.x - __bfloat162float(h0));
    __nv_bfloat16 l1 = __float2bfloat16(v.y - __bfloat162float(h1));
    __nv_bfloat16 l2 = __float2bfloat16(v.z - __bfloat162float(h2));
    __nv_bfloat16 l3 = __float2bfloat16(v.w - __bfloat162float(h3));
    __nv_bfloat162 hp0 = __halves2bfloat162(h0, h1);
    __nv_bfloat162 hp1 = __halves2bfloat162(h2, h3);
    __nv_bfloat162 lp0 = __halves2bfloat162(l0, l1);
    __nv_bfloat162 lp1 = __halves2bfloat162(l2, l3);
    uint2 hw, lw;
    hw.x = *(uint32_t*)&hp0; hw.y = *(uint32_t*)&hp1;
    lw.x = *(uint32_t*)&lp0; lw.y = *(uint32_t*)&lp1;
    *(uint2*)&hi[i] = hw;
    *(uint2*)&lo[i] = lw;
}

// ---------------------------------------------------------------------------
// Split-bf16 tensor-core GEMM via mma.sync (baseline ISA):
//   C[M,N] = A[M,K] * B[N,K]^T  fp32 accumulate,
//   D += Ahi*Bhi + Ahi*Blo + Alo*Bhi.
// CTA 128x128, BK=32, 8 warps (2Mx4N), warp tile 64x32.
// Smem rows padded to 80B -> conflict-free ldmatrix, no swizzle needed.
// ---------------------------------------------------------------------------
constexpr int MT_ROWB  = 80;                 // padded row stride (bytes)
constexpr int MT_TILEB = 128 * MT_ROWB;      // 10240 B per tile
constexpr int MT_STAGE = 4 * MT_TILEB;       // Ahi,Alo,Bhi,Blo = 40960 B
constexpr size_t MT_SMEM = 2 * (size_t)MT_STAGE;   // 81920 B

__global__ __launch_bounds__(256, 1) void mma_gemm_kernel(
    const __nv_bfloat16* __restrict__ Ahi, const __nv_bfloat16* __restrict__ Alo,
    const __nv_bfloat16* __restrict__ Bhi, const __nv_bfloat16* __restrict__ Blo,
    float* __restrict__ C, int M, int N, int K)
{
    extern __shared__ __align__(256) char smem[];
    const uint32_t sbase = smem_u32(smem);
    const int tid = threadIdx.x;
    const int wid = tid >> 5;
    const int lid = tid & 31;
    const int m0 = blockIdx.y * 128;
    const int n0 = blockIdx.x * 128;
    const int warp_m = (wid & 1) * 64;
    const int warp_n = (wid >> 1) * 32;

    const __nv_bfloat16* srcs[4] = {
        Ahi + (size_t)m0 * K, Alo + (size_t)m0 * K,
        Bhi + (size_t)n0 * K, Blo + (size_t)n0 * K };

    const int nchunks = K >> 5;              // K/32

    // ---- async stage loader: stage c -> buffer (c&1) ----
    auto load_stage = [&](int c) {
        const uint32_t stg = sbase + (uint32_t)(c & 1) * MT_STAGE;
        const int k0 = c << 5;
#pragma unroll
        for (int t = 0; t < 4; t++) {
            const __nv_bfloat16* src = srcs[t] + k0;
            const uint32_t sdst = stg + t * MT_TILEB;
#pragma unroll
            for (int i = 0; i < 2; i++) {
                int idx   = tid + i * 256;         // 0..511
                int row   = idx >> 2;
                int chunk = idx & 3;
                uint32_t d = sdst + row * MT_ROWB + chunk * 16;
                const void* g = (const void*)(src + (size_t)row * K + chunk * 8);
                asm volatile("cp.async.cg.shared.global [%0], [%1], 16;"
                             :: "r"(d), "l"(g));
            }
        }
        CP_COMMIT();
    };

    float acc[4][4][4];
#pragma unroll
    for (int mt = 0; mt < 4; mt++)
#pragma unroll
        for (int nt = 0; nt < 4; nt++)
#pragma unroll
            for (int e = 0; e < 4; e++) acc[mt][nt][e] = 0.f;

    load_stage(0);
    load_stage(1);

    // ldmatrix lane-address components
    const int matA = lid >> 3;
    const int rA   = (lid & 7) + ((matA & 1) << 3);   // A: mat0 r0-7,k0; mat1 r8-15,k0; mat2/3 k8
    const int kcA  = matA >> 1;
    const int nB   = (lid & 7) + ((matA >> 1) << 3);  // B: mat0 n0-7,k0; mat1 n0-7,k8; mat2/3 n8-15
    const int kcB  = matA & 1;

    for (int c = 0; c < nchunks; c++) {
        if (c + 1 < nchunks) {
            asm volatile("cp.async.wait_group 1;" ::: "memory");
        } else {
            asm volatile("cp.async.wait_group 0;" ::: "memory");
        }
        __syncthreads();

        const uint32_t stg = sbase + (uint32_t)(c & 1) * MT_STAGE;
        const uint32_t Ah = stg;
        const uint32_t Al = stg + MT_TILEB;
        const uint32_t Bh = stg + 2 * MT_TILEB;
        const uint32_t Bl = stg + 3 * MT_TILEB;

#pragma unroll
        for (int ks = 0; ks < 2; ks++) {
            const int kbyte = ks * 32;
            uint32_t ahi[4][4], alo[4][4], bhi[4][2], blo[4][2];
#pragma unroll
            for (int mt = 0; mt < 4; mt++) {
                uint32_t ra = (uint32_t)((warp_m + mt * 16 + rA) * MT_ROWB
                                         + kbyte + kcA * 16);
                ldsm4(ahi[mt], Ah + ra);
                ldsm4(alo[mt], Al + ra);
            }
#pragma unroll
            for (int ntp = 0; ntp < 2; ntp++) {
                uint32_t rb = (uint32_t)((warp_n + ntp * 16 + nB) * MT_ROWB
                                         + kbyte + kcB * 16);
                uint32_t th[4], tl[4];
                ldsm4(th, Bh + rb);
                ldsm4(tl, Bl + rb);
                bhi[ntp * 2][0] = th[0]; bhi[ntp * 2][1] = th[1];
                bhi[ntp * 2 + 1][0] = th[2]; bhi[ntp * 2 + 1][1] = th[3];
                blo[ntp * 2][0] = tl[0]; blo[ntp * 2][1] = tl[1];
                blo[ntp * 2 + 1][0] = tl[2]; blo[ntp * 2 + 1][1] = tl[3];
            }
#pragma unroll
            for (int mt = 0; mt < 4; mt++)
#pragma unroll
                for (int nt = 0; nt < 4; nt++) {
                    mma16816(acc[mt][nt], ahi[mt], bhi[nt]);
                    mma16816(acc[mt][nt], ahi[mt], blo[nt]);
                    mma16816(acc[mt][nt], alo[mt], bhi[nt]);
                }
        }
        __syncthreads();
        if (c + 2 < nchunks) load_stage(c + 2);
    }

    // Epilogue: fp32 stores, float2 per half-tile row
#pragma unroll
    for (int mt = 0; mt < 4; mt++) {
        int r = m0 + warp_m + mt * 16 + (lid >> 2);
#pragma unroll
        for (int nt = 0; nt < 4; nt++) {
            int cn = n0 + warp_n + nt * 8 + 2 * (lid & 3);
            *(float2*)&C[(size_t)r * N + cn] =
                make_float2(acc[mt][nt][0], acc[mt][nt][1]);
            *(float2*)&C[(size_t)(r + 8) * N + cn] =
                make_float2(acc[mt][nt][2], acc[mt][nt][3]);
        }
    }
}

// ---------------------------------------------------------------------------
// RoPE + transpose:  in [B,S,H*DK] -> out [B,H,DK,S]
// ---------------------------------------------------------------------------
__global__ __launch_bounds__(256) void rope_transpose_kernel(
    const float* __restrict__ in, const float* __restrict__ cosd,
    const float* __restrict__ sind, float* __restrict__ out)
{
    __shared__ float tile[128][33];
    const int b  = blockIdx.z;
    const int h  = blockIdx.y;
    const int s0 = blockIdx.x * 32;
    const int tid = threadIdx.x;

#pragma unroll
    for (int i = 0; i < 8; i++) {
        int item = tid + i * 256;
        int sl = item >> 6;
        int j  = item & 63;
        int s  = s0 + sl;
        float2 xp = *(const float2*)&in[(size_t)(b * Ss + s) * Dd + h * DK + 2 * j];
        float c  = cosd[s * 64 + j];
        float sn = sind[s * 64 + j];
        tile[2 * j][sl]     = xp.x * c - xp.y * sn;
        tile[2 * j + 1][sl] = xp.y * c + xp.x * sn;
    }
    __syncthreads();
#pragma unroll
    for (int i = 0; i < 16; i++) {
        int item = tid + i * 256;
        int dk = item >> 5;
        int sl = item & 31;
        out[(size_t)((b * Hh + h) * DK + dk) * Ss + s0 + sl] = tile[dk][sl];
    }
}

// ---------------------------------------------------------------------------
// Flash attention (causal, online softmax), fp32 SIMT.
// ---------------------------------------------------------------------------
constexpr int FL_Q  = 128 * 68;
constexpr int FL_K  = 128 * 68;
constexpr int FL_V  = 64 * 132;
constexpr int FL_P  = 64 * 68;
constexpr size_t FL_SMEM = (size_t)(FL_Q + FL_K + FL_V + FL_P) * sizeof(float);

__global__ __launch_bounds__(256) void flash_kernel(
    const float* __restrict__ qt, const float* __restrict__ kt,
    const float* __restrict__ v, float* __restrict__ o)
{
    extern __shared__ float sm[];
    float* Qs = sm;
    float* Ks = sm + FL_Q;
    float* Vs = Ks + FL_K;
    float* Ps = Vs + FL_V;

    const int qb = blockIdx.x;
    const int h  = blockIdx.y;
    const int b  = blockIdx.z;
    const int tid = threadIdx.x;
    const int tx = tid & 15;
    const int ty = tid >> 4;
    const float scale = 0.08838834764831845f;

    const float* qbase = qt + (size_t)(b * Hh + h) * DK * Ss + qb * 64;
#pragma unroll
    for (int i = 0; i < 8; i++) {
        int f  = tid + i * 256;
        int k  = f >> 4;
        int rc = (f & 15) << 2;
        *(float4*)&Qs[k * 68 + rc] = *(const float4*)&qbase[(size_t)k * Ss + rc];
    }

    float m_i[4], l_i[4], accO[4][8];
#pragma unroll
    for (int i = 0; i < 4; i++) {
        m_i[i] = -1e30f; l_i[i] = 0.f;
#pragma unroll
        for (int j = 0; j < 8; j++) accO[i][j] = 0.f;
    }

    const float* kbase0 = kt + (size_t)(b * Hh + h) * DK * Ss;
    const float* vbase  = v + (size_t)b * Ss * Dd + h * DK;

    for (int kb = 0; kb <= qb; kb++) {
        __syncthreads();
        const float* kbase = kbase0 + kb * 64;
#pragma unroll
        for (int i = 0; i < 8; i++) {
            int f  = tid + i * 256;
            int k  = f >> 4;
            int rc = (f & 15) << 2;
            *(float4*)&Ks[k * 68 + rc] = *(const float4*)&kbase[(size_t)k * Ss + rc];
        }
#pragma unroll
        for (int i = 0; i < 8; i++) {
            int f  = tid + i * 256;
            int c  = f >> 5;
            int dc = (f & 31) << 2;
            *(float4*)&Vs[c * 132 + dc] =
                *(const float4*)&vbase[(size_t)(kb * 64 + c) * Dd + dc];
        }
        __syncthreads();

        float sc[4][4];
#pragma unroll
        for (int i = 0; i < 4; i++)
#pragma unroll
            for (int j = 0; j < 4; j++) sc[i][j] = 0.f;

#pragma unroll 4
        for (int k = 0; k < 128; k++) {
            float4 a = *(float4*)&Qs[k * 68 + 4 * ty];
            float4 bq = *(float4*)&Ks[k * 68 + 4 * tx];
            float ar[4] = {a.x, a.y, a.z, a.w};
            float br[4] = {bq.x, bq.y, bq.z, bq.w};
#pragma unroll
            for (int i = 0; i < 4; i++)
#pragma unroll
                for (int j = 0; j < 4; j++)
                    sc[i][j] = fmaf(ar[i], br[j], sc[i][j]);
        }

        const bool diag = (kb == qb);
#pragma unroll
        for (int i = 0; i < 4; i++)
#pragma unroll
            for (int j = 0; j < 4; j++) {
                float s = sc[i][j] * scale;
                if (diag && (4 * tx + j > 4 * ty + i)) s = -1e30f;
                sc[i][j] = s;
            }

#pragma unroll
        for (int i = 0; i < 4; i++) {
            float rm = fmaxf(fmaxf(sc[i][0], sc[i][1]), fmaxf(sc[i][2], sc[i][3]));
#pragma unroll
            for (int off = 8; off >= 1; off >>= 1)
                rm = fmaxf(rm, __shfl_xor_sync(0xffffffffu, rm, off));
            float mnew  = fmaxf(m_i[i], rm);
            float alpha = __expf(m_i[i] - mnew);
            float rs = 0.f;
#pragma unroll
            for (int j = 0; j < 4; j++) {
                float p = __expf(sc[i][j] - mnew);
                Ps[(4 * ty + i) * 68 + 4 * tx + j] = p;
                rs += p;
            }
#pragma unroll
            for (int off = 8; off >= 1; off >>= 1)
                rs += __shfl_xor_sync(0xffffffffu, rs, off);
            l_i[i] = l_i[i] * alpha + rs;
            m_i[i] = mnew;
#pragma unroll
            for (int j = 0; j < 8; j++) accO[i][j] *= alpha;
        }
        __syncthreads();

#pragma unroll 2
        for (int c = 0; c < 64; c++) {
            float4 v0 = *(float4*)&Vs[c * 132 + 8 * tx];
            float4 v1 = *(float4*)&Vs[c * 132 + 8 * tx + 4];
            float vr[8] = {v0.x, v0.y, v0.z, v0.w, v1.x, v1.y, v1.z, v1.w};
#pragma unroll
            for (int i = 0; i < 4; i++) {
                float p = Ps[(4 * ty + i) * 68 + c];
#pragma unroll
                for (int j = 0; j < 8; j++)
                    accO[i][j] = fmaf(p, vr[j], accO[i][j]);
            }
        }
    }

#pragma unroll
    for (int i = 0; i < 4; i++) {
        int row = qb * 64 + 4 * ty + i;
        float inv = 1.f / l_i[i];
        float4 o0 = make_float4(accO[i][0] * inv, accO[i][1] * inv,
                                accO[i][2] * inv, accO[i][3] * inv);
        float4 o1 = make_float4(accO[i][4] * inv, accO[i][5] * inv,
                                accO[i][6] * inv, accO[i][7] * inv);
        size_t base = (size_t)(b * Ss + row) * Dd + h * DK + 8 * tx;
        *(float4*)&o[base]     = o0;
        *(float4*)&o[base + 4] = o1;
    }
}

// ---------------------------------------------------------------------------
// Launch
// ---------------------------------------------------------------------------
extern "C" void kernel_launch(void* const* d_in, const int* in_sizes, int n_in,
                              void* d_out, int out_size)
{
    (void)in_sizes; (void)n_in; (void)out_size;
    const float* x    = (const float*)d_in[0];
    const float* Wq   = (const float*)d_in[1];
    const float* Wk   = (const float*)d_in[2];
    const float* Wv   = (const float*)d_in[3];
    const float* Wo   = (const float*)d_in[4];
    const float* cosd = (const float*)d_in[5];
    const float* sind = (const float*)d_in[6];
    float* out = (float*)d_out;

    float *qlin, *klin, *vlin, *qt, *ktp;
    __nv_bfloat16 *xhi, *xlo, *whi, *wlo;
    cudaGetSymbolAddress((void**)&qlin, g_qlin);
    cudaGetSymbolAddress((void**)&klin, g_klin);
    cudaGetSymbolAddress((void**)&vlin, g_vlin);
    cudaGetSymbolAddress((void**)&qt,   g_qt);
    cudaGetSymbolAddress((void**)&ktp,  g_kt);
    cudaGetSymbolAddress((void**)&xhi,  g_xhi);
    cudaGetSymbolAddress((void**)&xlo,  g_xlo);
    cudaGetSymbolAddress((void**)&whi,  g_whi);
    cudaGetSymbolAddress((void**)&wlo,  g_wlo);

    cudaFuncSetAttribute(flash_kernel,
                         cudaFuncAttributeMaxDynamicSharedMemorySize, (int)FL_SMEM);
    cudaFuncSetAttribute(mma_gemm_kernel,
                         cudaFuncAttributeMaxDynamicSharedMemorySize, (int)MT_SMEM);

    const size_t wN = (size_t)Dd * Dd;
    const int   nX = Mm * Dd;
    const int   nW = (int)wN;

    // Split inputs to bf16 hi/lo
    split_kernel<<<nX / 4 / 256, 256>>>(x,  xhi, xlo, nX);
    split_kernel<<<nW / 4 / 256, 256>>>(Wq, whi + 0 * wN, wlo + 0 * wN, nW);
    split_kernel<<<nW / 4 / 256, 256>>>(Wk, whi + 1 * wN, wlo + 1 * wN, nW);
    split_kernel<<<nW / 4 / 256, 256>>>(Wv, whi + 2 * wN, wlo + 2 * wN, nW);
    split_kernel<<<nW / 4 / 256, 256>>>(Wo, whi + 3 * wN, wlo + 3 * wN, nW);

    // QKV projections on tensor cores (mma.sync path)
    dim3 tgrid(Dd / 128, Mm / 128);
    mma_gemm_kernel<<<tgrid, 256, MT_SMEM>>>(xhi, xlo, whi + 0 * wN, wlo + 0 * wN,
                                             qlin, Mm, Dd, Dd);
    mma_gemm_kernel<<<tgrid, 256, MT_SMEM>>>(xhi, xlo, whi + 1 * wN, wlo + 1 * wN,
                                             klin, Mm, Dd, Dd);
    mma_gemm_kernel<<<tgrid, 256, MT_SMEM>>>(xhi, xlo, whi + 2 * wN, wlo + 2 * wN,
                                             vlin, Mm, Dd, Dd);

    dim3 rgrid(Ss / 32, Hh, Bb);
    rope_transpose_kernel<<<rgrid, 256>>>(qlin, cosd, sind, qt);
    rope_transpose_kernel<<<rgrid, 256>>>(klin, cosd, sind, ktp);

    dim3 fgrid(Ss / 64, Hh, Bb);
    flash_kernel<<<fgrid, 256, FL_SMEM>>>(qt, ktp, vlin, qlin /* reused as O */);

    // Output projection: split attention output, then tensor-core GEMM
    split_kernel<<<nX / 4 / 256, 256>>>(qlin, xhi, xlo, nX);
    mma_gemm_kernel<<<tgrid, 256, MT_SMEM>>>(xhi, xlo, whi + 3 * wN, wlo + 3 * wN,
                                             out, Mm, Dd, Dd);
}

// round 6
// speedup vs baseline: 2.3505x; 1.5538x over previous
#include <cuda_runtime.h>
#include <cuda_bf16.h>
#include <cstdint>

// Problem constants
constexpr int Bb  = 4;
constexpr int Ss  = 2048;
constexpr int Dd  = 2048;
constexpr int Hh  = 16;
constexpr int DK  = 128;
constexpr int Mm  = Bb * Ss;          // 8192 rows

// ---------------------------------------------------------------------------
// Scratch (static __device__ arrays)
// ---------------------------------------------------------------------------
__device__ float g_qlin[(size_t)Mm * Dd];
__device__ float g_klin[(size_t)Mm * Dd];
__device__ float g_vlin[(size_t)Mm * Dd];

__device__ __align__(256) __nv_bfloat16 g_xhi[(size_t)Mm * Dd];
__device__ __align__(256) __nv_bfloat16 g_xlo[(size_t)Mm * Dd];
__device__ __align__(256) __nv_bfloat16 g_whi[4][(size_t)Dd * Dd];
__device__ __align__(256) __nv_bfloat16 g_wlo[4][(size_t)Dd * Dd];

// flash operands, [B,H,S,DK] for Q/K and [B,H,DK,S] for Vt
constexpr size_t FSZ = (size_t)Bb * Hh * Ss * DK;
__device__ __align__(256) __nv_bfloat16 g_qsh[FSZ];
__device__ __align__(256) __nv_bfloat16 g_qsl[FSZ];
__device__ __align__(256) __nv_bfloat16 g_ksh[FSZ];
__device__ __align__(256) __nv_bfloat16 g_ksl[FSZ];
__device__ __align__(256) __nv_bfloat16 g_vth[FSZ];
__device__ __align__(256) __nv_bfloat16 g_vtl[FSZ];

// ---------------------------------------------------------------------------
// Baseline-ISA helpers
// ---------------------------------------------------------------------------
__device__ __forceinline__ uint32_t smem_u32(const void* p) {
    uint32_t a;
    asm("{ .reg .u64 t; cvta.to.shared.u64 t, %1; cvt.u32.u64 %0, t; }"
        : "=r"(a) : "l"(p));
    return a;
}
__device__ __forceinline__ void ldsm4(uint32_t* r, uint32_t addr) {
    asm volatile("ldmatrix.sync.aligned.m8n8.x4.shared.b16 {%0,%1,%2,%3}, [%4];"
                 : "=r"(r[0]), "=r"(r[1]), "=r"(r[2]), "=r"(r[3])
                 : "r"(addr));
}
__device__ __forceinline__ void mma16816(float* c, const uint32_t* a,
                                         const uint32_t* b) {
    asm volatile(
        "mma.sync.aligned.m16n8k16.row.col.f32.bf16.bf16.f32 "
        "{%0,%1,%2,%3}, {%4,%5,%6,%7}, {%8,%9}, {%0,%1,%2,%3};"
        : "+f"(c[0]), "+f"(c[1]), "+f"(c[2]), "+f"(c[3])
        : "r"(a[0]), "r"(a[1]), "r"(a[2]), "r"(a[3]), "r"(b[0]), "r"(b[1]));
}
#define CP_COMMIT() asm volatile("cp.async.commit_group;" ::: "memory")

__device__ __forceinline__ uint32_t pack_split(float x, float y, uint32_t& lo_out) {
    __nv_bfloat162 h = __floats2bfloat162_rn(x, y);
    float2 hb = __bfloat1622float2(h);
    __nv_bfloat162 l = __floats2bfloat162_rn(x - hb.x, y - hb.y);
    lo_out = *(uint32_t*)&l;
    return *(uint32_t*)&h;
}

// ---------------------------------------------------------------------------
// Split fp32 -> (bf16 hi, bf16 lo)
// ---------------------------------------------------------------------------
__global__ __launch_bounds__(256) void split_kernel(
    const float* __restrict__ in, __nv_bfloat16* __restrict__ hi,
    __nv_bfloat16* __restrict__ lo, int n)
{
    int i = (blockIdx.x * 256 + threadIdx.x) * 4;
    if (i >= n) return;
    float4 v = *(const float4*)&in[i];
    uint32_t l0, l1;
    uint32_t h0 = pack_split(v.x, v.y, l0);
    uint32_t h1 = pack_split(v.z, v.w, l1);
    *(uint2*)&hi[i] = make_uint2(h0, h1);
    *(uint2*)&lo[i] = make_uint2(l0, l1);
}

// ---------------------------------------------------------------------------
// Split-bf16 tensor-core GEMM via mma.sync (unchanged from R5; proven)
// ---------------------------------------------------------------------------
constexpr int MT_ROWB  = 80;
constexpr int MT_TILEB = 128 * MT_ROWB;
constexpr int MT_STAGE = 4 * MT_TILEB;
constexpr size_t MT_SMEM = 2 * (size_t)MT_STAGE;

__global__ __launch_bounds__(256, 1) void mma_gemm_kernel(
    const __nv_bfloat16* __restrict__ Ahi, const __nv_bfloat16* __restrict__ Alo,
    const __nv_bfloat16* __restrict__ Bhi, const __nv_bfloat16* __restrict__ Blo,
    float* __restrict__ C, int M, int N, int K)
{
    extern __shared__ __align__(256) char smem[];
    const uint32_t sbase = smem_u32(smem);
    const int tid = threadIdx.x;
    const int wid = tid >> 5;
    const int lid = tid & 31;
    const int m0 = blockIdx.y * 128;
    const int n0 = blockIdx.x * 128;
    const int warp_m = (wid & 1) * 64;
    const int warp_n = (wid >> 1) * 32;

    const __nv_bfloat16* srcs[4] = {
        Ahi + (size_t)m0 * K, Alo + (size_t)m0 * K,
        Bhi + (size_t)n0 * K, Blo + (size_t)n0 * K };

    const int nchunks = K >> 5;

    auto load_stage = [&](int c) {
        const uint32_t stg = sbase + (uint32_t)(c & 1) * MT_STAGE;
        const int k0 = c << 5;
#pragma unroll
        for (int t = 0; t < 4; t++) {
            const __nv_bfloat16* src = srcs[t] + k0;
            const uint32_t sdst = stg + t * MT_TILEB;
#pragma unroll
            for (int i = 0; i < 2; i++) {
                int idx   = tid + i * 256;
                int row   = idx >> 2;
                int chunk = idx & 3;
                uint32_t d = sdst + row * MT_ROWB + chunk * 16;
                const void* g = (const void*)(src + (size_t)row * K + chunk * 8);
                asm volatile("cp.async.cg.shared.global [%0], [%1], 16;"
                             :: "r"(d), "l"(g));
            }
        }
        CP_COMMIT();
    };

    float acc[4][4][4];
#pragma unroll
    for (int mt = 0; mt < 4; mt++)
#pragma unroll
        for (int nt = 0; nt < 4; nt++)
#pragma unroll
            for (int e = 0; e < 4; e++) acc[mt][nt][e] = 0.f;

    load_stage(0);
    load_stage(1);

    const int matA = lid >> 3;
    const int rA   = (lid & 7) + ((matA & 1) << 3);
    const int kcA  = matA >> 1;
    const int nB   = (lid & 7) + ((matA >> 1) << 3);
    const int kcB  = matA & 1;

    for (int c = 0; c < nchunks; c++) {
        if (c + 1 < nchunks) {
            asm volatile("cp.async.wait_group 1;" ::: "memory");
        } else {
            asm volatile("cp.async.wait_group 0;" ::: "memory");
        }
        __syncthreads();

        const uint32_t stg = sbase + (uint32_t)(c & 1) * MT_STAGE;
        const uint32_t Ah = stg;
        const uint32_t Al = stg + MT_TILEB;
        const uint32_t Bh = stg + 2 * MT_TILEB;
        const uint32_t Bl = stg + 3 * MT_TILEB;

#pragma unroll
        for (int ks = 0; ks < 2; ks++) {
            const int kbyte = ks * 32;
            uint32_t ahi[4][4], alo[4][4], bhi[4][2], blo[4][2];
#pragma unroll
            for (int mt = 0; mt < 4; mt++) {
                uint32_t ra = (uint32_t)((warp_m + mt * 16 + rA) * MT_ROWB
                                         + kbyte + kcA * 16);
                ldsm4(ahi[mt], Ah + ra);
                ldsm4(alo[mt], Al + ra);
            }
#pragma unroll
            for (int ntp = 0; ntp < 2; ntp++) {
                uint32_t rb = (uint32_t)((warp_n + ntp * 16 + nB) * MT_ROWB
                                         + kbyte + kcB * 16);
                uint32_t th[4], tl[4];
                ldsm4(th, Bh + rb);
                ldsm4(tl, Bl + rb);
                bhi[ntp * 2][0] = th[0]; bhi[ntp * 2][1] = th[1];
                bhi[ntp * 2 + 1][0] = th[2]; bhi[ntp * 2 + 1][1] = th[3];
                blo[ntp * 2][0] = tl[0]; blo[ntp * 2][1] = tl[1];
                blo[ntp * 2 + 1][0] = tl[2]; blo[ntp * 2 + 1][1] = tl[3];
            }
#pragma unroll
            for (int mt = 0; mt < 4; mt++)
#pragma unroll
                for (int nt = 0; nt < 4; nt++) {
                    mma16816(acc[mt][nt], ahi[mt], bhi[nt]);
                    mma16816(acc[mt][nt], ahi[mt], blo[nt]);
                    mma16816(acc[mt][nt], alo[mt], bhi[nt]);
                }
        }
        __syncthreads();
        if (c + 2 < nchunks) load_stage(c + 2);
    }

#pragma unroll
    for (int mt = 0; mt < 4; mt++) {
        int r = m0 + warp_m + mt * 16 + (lid >> 2);
#pragma unroll
        for (int nt = 0; nt < 4; nt++) {
            int cn = n0 + warp_n + nt * 8 + 2 * (lid & 3);
            *(float2*)&C[(size_t)r * N + cn] =
                make_float2(acc[mt][nt][0], acc[mt][nt][1]);
            *(float2*)&C[(size_t)(r + 8) * N + cn] =
                make_float2(acc[mt][nt][2], acc[mt][nt][3]);
        }
    }
}

// ---------------------------------------------------------------------------
// RoPE + split:  in [B,S,H*DK] fp32 -> hi/lo bf16 [B,H,S,DK], optional scale
// grid (S/64, H, B), 256 threads
// ---------------------------------------------------------------------------
__global__ __launch_bounds__(256) void rope_split_kernel(
    const float* __restrict__ in, const float* __restrict__ cosd,
    const float* __restrict__ sind, __nv_bfloat16* __restrict__ hi,
    __nv_bfloat16* __restrict__ lo, float scale)
{
    const int b  = blockIdx.z;
    const int h  = blockIdx.y;
    const int s0 = blockIdx.x * 64;
    const int tid = threadIdx.x;
#pragma unroll
    for (int i = 0; i < 16; i++) {
        int p  = tid + i * 256;          // 64 s * 64 pairs
        int sl = p >> 6;
        int j  = p & 63;
        int s  = s0 + sl;
        float2 xp = *(const float2*)&in[(size_t)(b * Ss + s) * Dd + h * DK + 2 * j];
        float c  = cosd[s * 64 + j];
        float sn = sind[s * 64 + j];
        float e = (xp.x * c - xp.y * sn) * scale;
        float o = (xp.y * c + xp.x * sn) * scale;
        uint32_t lw;
        uint32_t hw = pack_split(e, o, lw);
        size_t idx = ((size_t)(b * Hh + h) * Ss + s) * DK + 2 * j;
        *(uint32_t*)&hi[idx] = hw;
        *(uint32_t*)&lo[idx] = lw;
    }
}

// ---------------------------------------------------------------------------
// V transpose + split: vlin [B,S,H*DK] fp32 -> hi/lo bf16 [B,H,DK,S]
// grid (S/32, H, B)
// ---------------------------------------------------------------------------
__global__ __launch_bounds__(256) void vt_split_kernel(
    const float* __restrict__ in, __nv_bfloat16* __restrict__ hi,
    __nv_bfloat16* __restrict__ lo)
{
    __shared__ float tile[128][33];
    const int b  = blockIdx.z;
    const int h  = blockIdx.y;
    const int s0 = blockIdx.x * 32;
    const int tid = threadIdx.x;
#pragma unroll
    for (int i = 0; i < 16; i++) {
        int idx = tid + i * 256;         // 32 s x 128 dk
        int sl  = idx >> 7;
        int dk  = idx & 127;
        tile[dk][sl] = in[(size_t)(b * Ss + s0 + sl) * Dd + h * DK + dk];
    }
    __syncthreads();
#pragma unroll
    for (int i = 0; i < 16; i++) {
        int idx = tid + i * 256;
        int dk  = idx >> 5;
        int sl  = idx & 31;
        float v = tile[dk][sl];
        __nv_bfloat16 hv = __float2bfloat16(v);
        __nv_bfloat16 lv = __float2bfloat16(v - __bfloat162float(hv));
        size_t a = ((size_t)(b * Hh + h) * DK + dk) * Ss + s0 + sl;
        hi[a] = hv;
        lo[a] = lv;
    }
}

// ---------------------------------------------------------------------------
// Flash attention on mma.sync (split-bf16, causal, online softmax).
// grid (S/128, H, B); 256 threads; warp w owns q rows 16w..16w+15.
// Q,K smem K-major [rows][DK], Vt smem [dk][s]; P stays in registers.
// Output written as bf16 hi/lo split directly (input to Wo GEMM).
// ---------------------------------------------------------------------------
constexpr int FQ_ROWB = 272;                  // 128 bf16 = 256B + 16 pad
constexpr int FK_ROWB = 272;
constexpr int FV_ROWB = 144;                  // 64 bf16 = 128B + 16 pad
constexpr int FQ_TILE = 128 * FQ_ROWB;        // 34816
constexpr int FK_TILE = 64 * FK_ROWB;         // 17408
constexpr int FV_TILE = 128 * FV_ROWB;        // 18432
constexpr int FKV_STAGE = 2 * FK_TILE + 2 * FV_TILE;   // 71680
constexpr int FKV_OFF = 2 * FQ_TILE;          // 69632
constexpr size_t FL2_SMEM = (size_t)FKV_OFF + 2 * FKV_STAGE;   // 212992

__global__ __launch_bounds__(256, 1) void flash_mma_kernel(
    const __nv_bfloat16* __restrict__ qhi_, const __nv_bfloat16* __restrict__ qlo_,
    const __nv_bfloat16* __restrict__ khi_, const __nv_bfloat16* __restrict__ klo_,
    const __nv_bfloat16* __restrict__ vth_, const __nv_bfloat16* __restrict__ vtl_,
    __nv_bfloat16* __restrict__ ohi, __nv_bfloat16* __restrict__ olo)
{
    extern __shared__ __align__(256) char smem[];
    const uint32_t sbase = smem_u32(smem);
    const int qb  = blockIdx.x;
    const int h   = blockIdx.y;
    const int b   = blockIdx.z;
    const int tid = threadIdx.x;
    const int wid = tid >> 5;
    const int lid = tid & 31;
    const int g   = lid >> 2;
    const int t4  = lid & 3;

    const size_t qoff = ((size_t)(b * Hh + h) * Ss + qb * 128) * DK;
    const size_t koff = (size_t)(b * Hh + h) * Ss * DK;
    const size_t voff = (size_t)(b * Hh + h) * DK * Ss;

    // Q tiles (hi, lo) -> smem
#pragma unroll
    for (int t = 0; t < 2; t++) {
        const __nv_bfloat16* src = (t ? qlo_ : qhi_) + qoff;
        const uint32_t sdst = sbase + t * FQ_TILE;
#pragma unroll
        for (int i = 0; i < 8; i++) {
            int idx = tid + i * 256;
            int row = idx >> 4;
            int ch  = idx & 15;
            asm volatile("cp.async.cg.shared.global [%0], [%1], 16;"
                         :: "r"(sdst + row * FQ_ROWB + ch * 16),
                            "l"((const void*)(src + (size_t)row * DK + ch * 8)));
        }
    }
    CP_COMMIT();

    auto load_kv = [&](int kb) {
        const uint32_t stg = sbase + FKV_OFF + (uint32_t)(kb & 1) * FKV_STAGE;
        const int s0 = kb * 64;
#pragma unroll
        for (int t = 0; t < 2; t++) {
            const __nv_bfloat16* src = (t ? klo_ : khi_) + koff;
            const uint32_t sdst = stg + t * FK_TILE;
#pragma unroll
            for (int i = 0; i < 4; i++) {
                int idx = tid + i * 256;
                int row = idx >> 4;
                int ch  = idx & 15;
                asm volatile("cp.async.cg.shared.global [%0], [%1], 16;"
                             :: "r"(sdst + row * FK_ROWB + ch * 16),
                                "l"((const void*)(src + (size_t)(s0 + row) * DK + ch * 8)));
            }
        }
#pragma unroll
        for (int t = 0; t < 2; t++) {
            const __nv_bfloat16* src = (t ? vtl_ : vth_) + voff;
            const uint32_t sdst = stg + 2 * FK_TILE + t * FV_TILE;
#pragma unroll
            for (int i = 0; i < 4; i++) {
                int idx = tid + i * 256;
                int row = idx >> 3;
                int ch  = idx & 7;
                asm volatile("cp.async.cg.shared.global [%0], [%1], 16;"
                             :: "r"(sdst + row * FV_ROWB + ch * 16),
                                "l"((const void*)(src + (size_t)row * Ss + s0 + ch * 8)));
            }
        }
        CP_COMMIT();
    };

    const int nkv = 2 * qb + 2;
    load_kv(0);
    load_kv(1);

    asm volatile("cp.async.wait_group 2;" ::: "memory");  // Q done
    __syncthreads();

    // ldmatrix lane components (proven mapping from mma_gemm_kernel)
    const int matA = lid >> 3;
    const int rA   = (lid & 7) + ((matA & 1) << 3);
    const int kcA  = matA >> 1;
    const int nB   = (lid & 7) + ((matA >> 1) << 3);
    const int kcB  = matA & 1;

    // Preload Q-hi A fragments (rows 16*wid..+15, all 8 k-steps)
    uint32_t qah[8][4];
    const uint32_t qrowaddr = sbase + (uint32_t)((wid * 16 + rA) * FQ_ROWB + kcA * 16);
#pragma unroll
    for (int kt = 0; kt < 8; kt++) ldsm4(qah[kt], qrowaddr + kt * 32);

    float oacc[16][4];
#pragma unroll
    for (int nt = 0; nt < 16; nt++)
#pragma unroll
        for (int e = 0; e < 4; e++) oacc[nt][e] = 0.f;
    float m0 = -1e30f, m1 = -1e30f, l0 = 0.f, l1 = 0.f;

    const int qrow0 = qb * 128 + wid * 16 + g;
    const int qrow1 = qrow0 + 8;

    for (int kb = 0; kb < nkv; kb++) {
        if (kb + 1 < nkv) {
            asm volatile("cp.async.wait_group 1;" ::: "memory");
        } else {
            asm volatile("cp.async.wait_group 0;" ::: "memory");
        }
        __syncthreads();
        const uint32_t stg = sbase + FKV_OFF + (uint32_t)(kb & 1) * FKV_STAGE;

        // ---- scores: 16 x 64 per warp ----
        float sacc[8][4];
#pragma unroll
        for (int nt = 0; nt < 8; nt++)
#pragma unroll
            for (int e = 0; e < 4; e++) sacc[nt][e] = 0.f;

#pragma unroll
        for (int kt = 0; kt < 8; kt++) {
            uint32_t qal[4];
            ldsm4(qal, qrowaddr + FQ_TILE + kt * 32);
#pragma unroll
            for (int ng = 0; ng < 4; ng++) {
                uint32_t rb = stg + (uint32_t)((ng * 16 + nB) * FK_ROWB + kt * 32 + kcB * 16);
                uint32_t th[4], tl[4];
                ldsm4(th, rb);
                ldsm4(tl, rb + FK_TILE);
                mma16816(sacc[2 * ng],     qah[kt], th);
                mma16816(sacc[2 * ng],     qah[kt], tl);
                mma16816(sacc[2 * ng],     qal,     th);
                mma16816(sacc[2 * ng + 1], qah[kt], th + 2);
                mma16816(sacc[2 * ng + 1], qah[kt], tl + 2);
                mma16816(sacc[2 * ng + 1], qal,     th + 2);
            }
        }

        // ---- causal mask (only needed for the last two kv tiles) ----
        if (kb >= 2 * qb) {
            const int kvb = kb * 64 + 2 * t4;
#pragma unroll
            for (int nt = 0; nt < 8; nt++) {
                int c0 = kvb + nt * 8;
                if (c0 > qrow0)     sacc[nt][0] = -1e30f;
                if (c0 + 1 > qrow0) sacc[nt][1] = -1e30f;
                if (c0 > qrow1)     sacc[nt][2] = -1e30f;
                if (c0 + 1 > qrow1) sacc[nt][3] = -1e30f;
            }
        }

        // ---- online softmax ----
        float rm0 = -1e30f, rm1 = -1e30f;
#pragma unroll
        for (int nt = 0; nt < 8; nt++) {
            rm0 = fmaxf(rm0, fmaxf(sacc[nt][0], sacc[nt][1]));
            rm1 = fmaxf(rm1, fmaxf(sacc[nt][2], sacc[nt][3]));
        }
        rm0 = fmaxf(rm0, __shfl_xor_sync(0xffffffffu, rm0, 1));
        rm0 = fmaxf(rm0, __shfl_xor_sync(0xffffffffu, rm0, 2));
        rm1 = fmaxf(rm1, __shfl_xor_sync(0xffffffffu, rm1, 1));
        rm1 = fmaxf(rm1, __shfl_xor_sync(0xffffffffu, rm1, 2));
        float mn0 = fmaxf(m0, rm0), mn1 = fmaxf(m1, rm1);
        float a0 = __expf(m0 - mn0), a1 = __expf(m1 - mn1);
        m0 = mn0; m1 = mn1;
        float rs0 = 0.f, rs1 = 0.f;
#pragma unroll
        for (int nt = 0; nt < 8; nt++) {
            sacc[nt][0] = __expf(sacc[nt][0] - mn0);
            sacc[nt][1] = __expf(sacc[nt][1] - mn0);
            sacc[nt][2] = __expf(sacc[nt][2] - mn1);
            sacc[nt][3] = __expf(sacc[nt][3] - mn1);
            rs0 += sacc[nt][0] + sacc[nt][1];
            rs1 += sacc[nt][2] + sacc[nt][3];
        }
        rs0 += __shfl_xor_sync(0xffffffffu, rs0, 1);
        rs0 += __shfl_xor_sync(0xffffffffu, rs0, 2);
        rs1 += __shfl_xor_sync(0xffffffffu, rs1, 1);
        rs1 += __shfl_xor_sync(0xffffffffu, rs1, 2);
        l0 = l0 * a0 + rs0;
        l1 = l1 * a1 + rs1;
#pragma unroll
        for (int nt = 0; nt < 16; nt++) {
            oacc[nt][0] *= a0; oacc[nt][1] *= a0;
            oacc[nt][2] *= a1; oacc[nt][3] *= a1;
        }

        // ---- PV: P (16x64) in regs, Vt in smem ----
#pragma unroll
        for (int kt2 = 0; kt2 < 4; kt2++) {
            uint32_t pah[4], pal[4];
            pah[0] = pack_split(sacc[2 * kt2][0],     sacc[2 * kt2][1],     pal[0]);
            pah[1] = pack_split(sacc[2 * kt2][2],     sacc[2 * kt2][3],     pal[1]);
            pah[2] = pack_split(sacc[2 * kt2 + 1][0], sacc[2 * kt2 + 1][1], pal[2]);
            pah[3] = pack_split(sacc[2 * kt2 + 1][2], sacc[2 * kt2 + 1][3], pal[3]);
#pragma unroll
            for (int ng = 0; ng < 8; ng++) {
                uint32_t rb = stg + 2 * FK_TILE
                            + (uint32_t)((ng * 16 + nB) * FV_ROWB + kt2 * 32 + kcB * 16);
                uint32_t vh[4], vl[4];
                ldsm4(vh, rb);
                ldsm4(vl, rb + FV_TILE);
                mma16816(oacc[2 * ng],     pah, vh);
                mma16816(oacc[2 * ng],     pah, vl);
                mma16816(oacc[2 * ng],     pal, vh);
                mma16816(oacc[2 * ng + 1], pah, vh + 2);
                mma16816(oacc[2 * ng + 1], pah, vl + 2);
                mma16816(oacc[2 * ng + 1], pal, vh + 2);
            }
        }
        __syncthreads();
        if (kb + 2 < nkv) load_kv(kb + 2);
    }

    // ---- epilogue: normalize, split to bf16 hi/lo, write [B,S,H*DK] ----
    const float inv0 = 1.f / l0, inv1 = 1.f / l1;
    const size_t base0 = (size_t)(b * Ss + qrow0) * Dd + h * DK;
    const size_t base1 = (size_t)(b * Ss + qrow1) * Dd + h * DK;
#pragma unroll
    for (int nt = 0; nt < 16; nt++) {
        int col = nt * 8 + 2 * t4;
        uint32_t lw0, lw1;
        uint32_t hw0 = pack_split(oacc[nt][0] * inv0, oacc[nt][1] * inv0, lw0);
        uint32_t hw1 = pack_split(oacc[nt][2] * inv1, oacc[nt][3] * inv1, lw1);
        *(uint32_t*)&ohi[base0 + col] = hw0;
        *(uint32_t*)&olo[base0 + col] = lw0;
        *(uint32_t*)&ohi[base1 + col] = hw1;
        *(uint32_t*)&olo[base1 + col] = lw1;
    }
}

// ---------------------------------------------------------------------------
// Launch
// ---------------------------------------------------------------------------
extern "C" void kernel_launch(void* const* d_in, const int* in_sizes, int n_in,
                              void* d_out, int out_size)
{
    (void)in_sizes; (void)n_in; (void)out_size;
    const float* x    = (const float*)d_in[0];
    const float* Wq   = (const float*)d_in[1];
    const float* Wk   = (const float*)d_in[2];
    const float* Wv   = (const float*)d_in[3];
    const float* Wo   = (const float*)d_in[4];
    const float* cosd = (const float*)d_in[5];
    const float* sind = (const float*)d_in[6];
    float* out = (float*)d_out;

    float *qlin, *klin, *vlin;
    __nv_bfloat16 *xhi, *xlo, *whi, *wlo;
    __nv_bfloat16 *qsh, *qsl, *ksh, *ksl, *vth, *vtl;
    cudaGetSymbolAddress((void**)&qlin, g_qlin);
    cudaGetSymbolAddress((void**)&klin, g_klin);
    cudaGetSymbolAddress((void**)&vlin, g_vlin);
    cudaGetSymbolAddress((void**)&xhi,  g_xhi);
    cudaGetSymbolAddress((void**)&xlo,  g_xlo);
    cudaGetSymbolAddress((void**)&whi,  g_whi);
    cudaGetSymbolAddress((void**)&wlo,  g_wlo);
    cudaGetSymbolAddress((void**)&qsh,  g_qsh);
    cudaGetSymbolAddress((void**)&qsl,  g_qsl);
    cudaGetSymbolAddress((void**)&ksh,  g_ksh);
    cudaGetSymbolAddress((void**)&ksl,  g_ksl);
    cudaGetSymbolAddress((void**)&vth,  g_vth);
    cudaGetSymbolAddress((void**)&vtl,  g_vtl);

    cudaFuncSetAttribute(mma_gemm_kernel,
                         cudaFuncAttributeMaxDynamicSharedMemorySize, (int)MT_SMEM);
    cudaFuncSetAttribute(flash_mma_kernel,
                         cudaFuncAttributeMaxDynamicSharedMemorySize, (int)FL2_SMEM);

    const size_t wN = (size_t)Dd * Dd;
    const int   nX = Mm * Dd;
    const int   nW = (int)wN;

    split_kernel<<<nX / 4 / 256, 256>>>(x,  xhi, xlo, nX);
    split_kernel<<<nW / 4 / 256, 256>>>(Wq, whi + 0 * wN, wlo + 0 * wN, nW);
    split_kernel<<<nW / 4 / 256, 256>>>(Wk, whi + 1 * wN, wlo + 1 * wN, nW);
    split_kernel<<<nW / 4 / 256, 256>>>(Wv, whi + 2 * wN, wlo + 2 * wN, nW);
    split_kernel<<<nW / 4 / 256, 256>>>(Wo, whi + 3 * wN, wlo + 3 * wN, nW);

    dim3 tgrid(Dd / 128, Mm / 128);
    mma_gemm_kernel<<<tgrid, 256, MT_SMEM>>>(xhi, xlo, whi + 0 * wN, wlo + 0 * wN,
                                             qlin, Mm, Dd, Dd);
    mma_gemm_kernel<<<tgrid, 256, MT_SMEM>>>(xhi, xlo, whi + 1 * wN, wlo + 1 * wN,
                                             klin, Mm, Dd, Dd);
    mma_gemm_kernel<<<tgrid, 256, MT_SMEM>>>(xhi, xlo, whi + 2 * wN, wlo + 2 * wN,
                                             vlin, Mm, Dd, Dd);

    const float scale = 0.08838834764831845f;   // 1/sqrt(128)
    dim3 rgrid(Ss / 64, Hh, Bb);
    rope_split_kernel<<<rgrid, 256>>>(qlin, cosd, sind, qsh, qsl, scale);
    rope_split_kernel<<<rgrid, 256>>>(klin, cosd, sind, ksh, ksl, 1.0f);
    dim3 vgrid(Ss / 32, Hh, Bb);
    vt_split_kernel<<<vgrid, 256>>>(vlin, vth, vtl);

    dim3 fgrid(Ss / 128, Hh, Bb);
    flash_mma_kernel<<<fgrid, 256, FL2_SMEM>>>(qsh, qsl, ksh, ksl, vth, vtl,
                                               xhi, xlo);

    mma_gemm_kernel<<<tgrid, 256, MT_SMEM>>>(xhi, xlo, whi + 3 * wN, wlo + 3 * wN,
                                             out, Mm, Dd, Dd);
}

// round 8
// speedup vs baseline: 2.3771x; 1.0113x over previous
#include <cuda_runtime.h>
#include <cuda_bf16.h>
#include <cstdint>

// Problem constants
constexpr int Bb  = 4;
constexpr int Ss  = 2048;
constexpr int Dd  = 2048;
constexpr int Hh  = 16;
constexpr int DK  = 128;
constexpr int Mm  = Bb * Ss;          // 8192 rows

// ---------------------------------------------------------------------------
// Scratch (static __device__ arrays)
// ---------------------------------------------------------------------------
__device__ __align__(256) __nv_bfloat16 g_xhi[(size_t)Mm * Dd];
__device__ __align__(256) __nv_bfloat16 g_xlo[(size_t)Mm * Dd];
__device__ __align__(256) __nv_bfloat16 g_whi[4][(size_t)Dd * Dd];
__device__ __align__(256) __nv_bfloat16 g_wlo[4][(size_t)Dd * Dd];

// Q/K (roped) and V, split bf16, natural [B,S,H*DK] layout
constexpr size_t FSZ = (size_t)Mm * Dd;
__device__ __align__(256) __nv_bfloat16 g_qsh[FSZ];
__device__ __align__(256) __nv_bfloat16 g_qsl[FSZ];
__device__ __align__(256) __nv_bfloat16 g_ksh[FSZ];
__device__ __align__(256) __nv_bfloat16 g_ksl[FSZ];
__device__ __align__(256) __nv_bfloat16 g_vsh[FSZ];
__device__ __align__(256) __nv_bfloat16 g_vsl[FSZ];

// ---------------------------------------------------------------------------
// Baseline-ISA helpers
// ---------------------------------------------------------------------------
__device__ __forceinline__ uint32_t smem_u32(const void* p) {
    uint32_t a;
    asm("{ .reg .u64 t; cvta.to.shared.u64 t, %1; cvt.u32.u64 %0, t; }"
        : "=r"(a) : "l"(p));
    return a;
}
__device__ __forceinline__ void ldsm4(uint32_t* r, uint32_t addr) {
    asm volatile("ldmatrix.sync.aligned.m8n8.x4.shared.b16 {%0,%1,%2,%3}, [%4];"
                 : "=r"(r[0]), "=r"(r[1]), "=r"(r[2]), "=r"(r[3])
                 : "r"(addr));
}
__device__ __forceinline__ void ldsm4t(uint32_t* r, uint32_t addr) {
    asm volatile("ldmatrix.sync.aligned.m8n8.x4.trans.shared.b16 {%0,%1,%2,%3}, [%4];"
                 : "=r"(r[0]), "=r"(r[1]), "=r"(r[2]), "=r"(r[3])
                 : "r"(addr));
}
__device__ __forceinline__ void mma16816(float* c, const uint32_t* a,
                                         const uint32_t* b) {
    asm volatile(
        "mma.sync.aligned.m16n8k16.row.col.f32.bf16.bf16.f32 "
        "{%0,%1,%2,%3}, {%4,%5,%6,%7}, {%8,%9}, {%0,%1,%2,%3};"
        : "+f"(c[0]), "+f"(c[1]), "+f"(c[2]), "+f"(c[3])
        : "r"(a[0]), "r"(a[1]), "r"(a[2]), "r"(a[3]), "r"(b[0]), "r"(b[1]));
}
#define CP_COMMIT() asm volatile("cp.async.commit_group;" ::: "memory")

__device__ __forceinline__ uint32_t pack_split(float x, float y, uint32_t& lo_out) {
    __nv_bfloat162 h = __floats2bfloat162_rn(x, y);
    float2 hb = __bfloat1622float2(h);
    __nv_bfloat162 l = __floats2bfloat162_rn(x - hb.x, y - hb.y);
    lo_out = *(uint32_t*)&l;
    return *(uint32_t*)&h;
}

// ---------------------------------------------------------------------------
// Split fp32 -> (bf16 hi, bf16 lo)
// ---------------------------------------------------------------------------
__global__ __launch_bounds__(256) void split_kernel(
    const float* __restrict__ in, __nv_bfloat16* __restrict__ hi,
    __nv_bfloat16* __restrict__ lo, int n)
{
    int i = (blockIdx.x * 256 + threadIdx.x) * 4;
    if (i >= n) return;
    float4 v = *(const float4*)&in[i];
    uint32_t l0, l1;
    uint32_t h0 = pack_split(v.x, v.y, l0);
    uint32_t h1 = pack_split(v.z, v.w, l1);
    *(uint2*)&hi[i] = make_uint2(h0, h1);
    *(uint2*)&lo[i] = make_uint2(l0, l1);
}

// ---------------------------------------------------------------------------
// Split-bf16 tensor-core GEMM via mma.sync, 3-stage pipeline, fused epilogues.
//   MODE 0: C fp32           MODE 1: Chi/Clo split bf16
//   MODE 2: RoPE (+scale) then split bf16
// C layout is always [M, N] row-major (addresses identical across modes).
// ---------------------------------------------------------------------------
constexpr int MT_ROWB  = 80;
constexpr int MT_TILEB = 128 * MT_ROWB;
constexpr int MT_STAGE = 4 * MT_TILEB;                 // 40960
constexpr size_t MT_SMEM = 3 * (size_t)MT_STAGE;       // 122880

template <int MODE>
__global__ __launch_bounds__(256, 1) void mma_gemm_kernel(
    const __nv_bfloat16* __restrict__ Ahi, const __nv_bfloat16* __restrict__ Alo,
    const __nv_bfloat16* __restrict__ Bhi, const __nv_bfloat16* __restrict__ Blo,
    float* __restrict__ C, __nv_bfloat16* __restrict__ Chi,
    __nv_bfloat16* __restrict__ Clo, const float* __restrict__ cosd,
    const float* __restrict__ sind, float scale, int M, int N, int K)
{
    extern __shared__ __align__(256) char smem[];
    const uint32_t sbase = smem_u32(smem);
    const int tid = threadIdx.x;
    const int wid = tid >> 5;
    const int lid = tid & 31;
    const int m0 = blockIdx.y * 128;
    const int n0 = blockIdx.x * 128;
    const int warp_m = (wid & 1) * 64;
    const int warp_n = (wid >> 1) * 32;

    const __nv_bfloat16* srcs[4] = {
        Ahi + (size_t)m0 * K, Alo + (size_t)m0 * K,
        Bhi + (size_t)n0 * K, Blo + (size_t)n0 * K };

    const int nchunks = K >> 5;

    auto load_stage = [&](int c, int buf) {
        const uint32_t stg = sbase + (uint32_t)buf * MT_STAGE;
        const int k0 = c << 5;
#pragma unroll
        for (int t = 0; t < 4; t++) {
            const __nv_bfloat16* src = srcs[t] + k0;
            const uint32_t sdst = stg + t * MT_TILEB;
#pragma unroll
            for (int i = 0; i < 2; i++) {
                int idx   = tid + i * 256;
                int row   = idx >> 2;
                int chunk = idx & 3;
                uint32_t d = sdst + row * MT_ROWB + chunk * 16;
                const void* g = (const void*)(src + (size_t)row * K + chunk * 8);
                asm volatile("cp.async.cg.shared.global [%0], [%1], 16;"
                             :: "r"(d), "l"(g));
            }
        }
        CP_COMMIT();
    };

    float acc[4][4][4];
#pragma unroll
    for (int mt = 0; mt < 4; mt++)
#pragma unroll
        for (int nt = 0; nt < 4; nt++)
#pragma unroll
            for (int e = 0; e < 4; e++) acc[mt][nt][e] = 0.f;

    load_stage(0, 0);
    load_stage(1, 1);
    load_stage(2, 2);

    const int matA = lid >> 3;
    const int rA   = (lid & 7) + ((matA & 1) << 3);
    const int kcA  = matA >> 1;
    const int nB   = (lid & 7) + ((matA >> 1) << 3);
    const int kcB  = matA & 1;

    int buf = 0;
    for (int c = 0; c < nchunks; c++) {
        if (c + 2 < nchunks) {
            asm volatile("cp.async.wait_group 2;" ::: "memory");
        } else if (c + 1 < nchunks) {
            asm volatile("cp.async.wait_group 1;" ::: "memory");
        } else {
            asm volatile("cp.async.wait_group 0;" ::: "memory");
        }
        __syncthreads();

        const uint32_t stg = sbase + (uint32_t)buf * MT_STAGE;
        const uint32_t Ah = stg;
        const uint32_t Al = stg + MT_TILEB;
        const uint32_t Bh = stg + 2 * MT_TILEB;
        const uint32_t Bl = stg + 3 * MT_TILEB;

#pragma unroll
        for (int ks = 0; ks < 2; ks++) {
            const int kbyte = ks * 32;
            uint32_t ahi[4][4], alo[4][4], bhi[4][2], blo[4][2];
#pragma unroll
            for (int mt = 0; mt < 4; mt++) {
                uint32_t ra = (uint32_t)((warp_m + mt * 16 + rA) * MT_ROWB
                                         + kbyte + kcA * 16);
                ldsm4(ahi[mt], Ah + ra);
                ldsm4(alo[mt], Al + ra);
            }
#pragma unroll
            for (int ntp = 0; ntp < 2; ntp++) {
                uint32_t rb = (uint32_t)((warp_n + ntp * 16 + nB) * MT_ROWB
                                         + kbyte + kcB * 16);
                uint32_t th[4], tl[4];
                ldsm4(th, Bh + rb);
                ldsm4(tl, Bl + rb);
                bhi[ntp * 2][0] = th[0]; bhi[ntp * 2][1] = th[1];
                bhi[ntp * 2 + 1][0] = th[2]; bhi[ntp * 2 + 1][1] = th[3];
                blo[ntp * 2][0] = tl[0]; blo[ntp * 2][1] = tl[1];
                blo[ntp * 2 + 1][0] = tl[2]; blo[ntp * 2 + 1][1] = tl[3];
            }
#pragma unroll
            for (int mt = 0; mt < 4; mt++)
#pragma unroll
                for (int nt = 0; nt < 4; nt++) {
                    mma16816(acc[mt][nt], ahi[mt], bhi[nt]);
                    mma16816(acc[mt][nt], ahi[mt], blo[nt]);
                    mma16816(acc[mt][nt], alo[mt], bhi[nt]);
                }
        }
        __syncthreads();
        if (c + 3 < nchunks) load_stage(c + 3, buf);
        buf = (buf == 2) ? 0 : buf + 1;
    }

    // ---- epilogue ----
#pragma unroll
    for (int mt = 0; mt < 4; mt++) {
        int r = m0 + warp_m + mt * 16 + (lid >> 2);
#pragma unroll
        for (int nt = 0; nt < 4; nt++) {
            int cn = n0 + warp_n + nt * 8 + 2 * (lid & 3);
            if (MODE == 0) {
                *(float2*)&C[(size_t)r * N + cn] =
                    make_float2(acc[mt][nt][0], acc[mt][nt][1]);
                *(float2*)&C[(size_t)(r + 8) * N + cn] =
                    make_float2(acc[mt][nt][2], acc[mt][nt][3]);
            } else if (MODE == 1) {
                uint32_t lw0, lw1;
                uint32_t hw0 = pack_split(acc[mt][nt][0], acc[mt][nt][1], lw0);
                uint32_t hw1 = pack_split(acc[mt][nt][2], acc[mt][nt][3], lw1);
                *(uint32_t*)&Chi[(size_t)r * N + cn]       = hw0;
                *(uint32_t*)&Clo[(size_t)r * N + cn]       = lw0;
                *(uint32_t*)&Chi[(size_t)(r + 8) * N + cn] = hw1;
                *(uint32_t*)&Clo[(size_t)(r + 8) * N + cn] = lw1;
            } else {
                int j  = (cn & (DK - 1)) >> 1;
                int s0_ = r & (Ss - 1);
                int s1_ = (r + 8) & (Ss - 1);
                float c0 = cosd[s0_ * 64 + j], n0_ = sind[s0_ * 64 + j];
                float c1 = cosd[s1_ * 64 + j], n1_ = sind[s1_ * 64 + j];
                float e0 = (acc[mt][nt][0] * c0 - acc[mt][nt][1] * n0_) * scale;
                float o0 = (acc[mt][nt][1] * c0 + acc[mt][nt][0] * n0_) * scale;
                float e1 = (acc[mt][nt][2] * c1 - acc[mt][nt][3] * n1_) * scale;
                float o1 = (acc[mt][nt][3] * c1 + acc[mt][nt][2] * n1_) * scale;
                uint32_t lw0, lw1;
                uint32_t hw0 = pack_split(e0, o0, lw0);
                uint32_t hw1 = pack_split(e1, o1, lw1);
                *(uint32_t*)&Chi[(size_t)r * N + cn]       = hw0;
                *(uint32_t*)&Clo[(size_t)r * N + cn]       = lw0;
                *(uint32_t*)&Chi[(size_t)(r + 8) * N + cn] = hw1;
                *(uint32_t*)&Clo[(size_t)(r + 8) * N + cn] = lw1;
            }
        }
    }
}

// ---------------------------------------------------------------------------
// Flash attention on mma.sync (split-bf16, causal, online softmax).
// Q/K/V read from natural [B,S,H*DK] bf16 split layout (row stride Dd).
// V consumed via ldmatrix.trans (no pre-transpose).
// grid (S/128, H, B); 256 threads; warp w owns q rows 16w..16w+15.
// ---------------------------------------------------------------------------
constexpr int FQ_ROWB = 272;                  // 128 bf16 = 256B + 16 pad
constexpr int FK_ROWB = 272;
constexpr int FV_ROWB = 272;
constexpr int FQ_TILE = 128 * FQ_ROWB;        // 34816
constexpr int FK_TILE = 64 * FK_ROWB;         // 17408
constexpr int FV_TILE = 64 * FV_ROWB;         // 17408
constexpr int FKV_STAGE = 2 * FK_TILE + 2 * FV_TILE;   // 69632
constexpr int FKV_OFF = 2 * FQ_TILE;          // 69632
constexpr size_t FL2_SMEM = (size_t)FKV_OFF + 2 * FKV_STAGE;   // 208896

__global__ __launch_bounds__(256, 1) void flash_mma_kernel(
    const __nv_bfloat16* __restrict__ qhi_, const __nv_bfloat16* __restrict__ qlo_,
    const __nv_bfloat16* __restrict__ khi_, const __nv_bfloat16* __restrict__ klo_,
    const __nv_bfloat16* __restrict__ vhi_, const __nv_bfloat16* __restrict__ vlo_,
    __nv_bfloat16* __restrict__ ohi, __nv_bfloat16* __restrict__ olo)
{
    extern __shared__ __align__(256) char smem[];
    const uint32_t sbase = smem_u32(smem);
    const int qb  = blockIdx.x;
    const int h   = blockIdx.y;
    const int b   = blockIdx.z;
    const int tid = threadIdx.x;
    const int wid = tid >> 5;
    const int lid = tid & 31;
    const int g   = lid >> 2;
    const int t4  = lid & 3;

    const size_t rowbase = (size_t)b * Ss;       // row index base into [B*S, Dd]
    const size_t hoff    = (size_t)h * DK;

    // Q tiles (hi, lo) -> smem, 128 rows x 256B, row stride Dd
#pragma unroll
    for (int t = 0; t < 2; t++) {
        const __nv_bfloat16* src = (t ? qlo_ : qhi_);
        const uint32_t sdst = sbase + t * FQ_TILE;
#pragma unroll
        for (int i = 0; i < 8; i++) {
            int idx = tid + i * 256;
            int row = idx >> 4;
            int ch  = idx & 15;
            const void* gp = (const void*)(src
                + (rowbase + qb * 128 + row) * Dd + hoff + ch * 8);
            asm volatile("cp.async.cg.shared.global [%0], [%1], 16;"
                         :: "r"(sdst + row * FQ_ROWB + ch * 16), "l"(gp));
        }
    }
    CP_COMMIT();

    auto load_kv = [&](int kb) {
        const uint32_t stg = sbase + FKV_OFF + (uint32_t)(kb & 1) * FKV_STAGE;
        const int s0 = kb * 64;
#pragma unroll
        for (int t = 0; t < 2; t++) {
            const __nv_bfloat16* src = (t ? klo_ : khi_);
            const uint32_t sdst = stg + t * FK_TILE;
#pragma unroll
            for (int i = 0; i < 4; i++) {
                int idx = tid + i * 256;
                int row = idx >> 4;
                int ch  = idx & 15;
                const void* gp = (const void*)(src
                    + (rowbase + s0 + row) * Dd + hoff + ch * 8);
                asm volatile("cp.async.cg.shared.global [%0], [%1], 16;"
                             :: "r"(sdst + row * FK_ROWB + ch * 16), "l"(gp));
            }
        }
#pragma unroll
        for (int t = 0; t < 2; t++) {
            const __nv_bfloat16* src = (t ? vlo_ : vhi_);
            const uint32_t sdst = stg + 2 * FK_TILE + t * FV_TILE;
#pragma unroll
            for (int i = 0; i < 4; i++) {
                int idx = tid + i * 256;
                int row = idx >> 4;
                int ch  = idx & 15;
                const void* gp = (const void*)(src
                    + (rowbase + s0 + row) * Dd + hoff + ch * 8);
                asm volatile("cp.async.cg.shared.global [%0], [%1], 16;"
                             :: "r"(sdst + row * FV_ROWB + ch * 16), "l"(gp));
            }
        }
        CP_COMMIT();
    };

    const int nkv = 2 * qb + 2;
    load_kv(0);
    load_kv(1);

    asm volatile("cp.async.wait_group 2;" ::: "memory");  // Q done
    __syncthreads();

    const int matA = lid >> 3;
    const int rA   = (lid & 7) + ((matA & 1) << 3);
    const int kcA  = matA >> 1;
    const int nB   = (lid & 7) + ((matA >> 1) << 3);
    const int kcB  = matA & 1;

    // Preload Q-hi A fragments
    uint32_t qah[8][4];
    const uint32_t qrowaddr = sbase + (uint32_t)((wid * 16 + rA) * FQ_ROWB + kcA * 16);
#pragma unroll
    for (int kt = 0; kt < 8; kt++) ldsm4(qah[kt], qrowaddr + kt * 32);

    float oacc[16][4];
#pragma unroll
    for (int nt = 0; nt < 16; nt++)
#pragma unroll
        for (int e = 0; e < 4; e++) oacc[nt][e] = 0.f;
    float m0 = -1e30f, m1 = -1e30f, l0 = 0.f, l1 = 0.f;

    const int qrow0 = qb * 128 + wid * 16 + g;
    const int qrow1 = qrow0 + 8;

    for (int kb = 0; kb < nkv; kb++) {
        if (kb + 1 < nkv) {
            asm volatile("cp.async.wait_group 1;" ::: "memory");
        } else {
            asm volatile("cp.async.wait_group 0;" ::: "memory");
        }
        __syncthreads();
        const uint32_t stg = sbase + FKV_OFF + (uint32_t)(kb & 1) * FKV_STAGE;

        // ---- scores: 16 x 64 per warp ----
        float sacc[8][4];
#pragma unroll
        for (int nt = 0; nt < 8; nt++)
#pragma unroll
            for (int e = 0; e < 4; e++) sacc[nt][e] = 0.f;

#pragma unroll
        for (int kt = 0; kt < 8; kt++) {
            uint32_t qal[4];
            ldsm4(qal, qrowaddr + FQ_TILE + kt * 32);
#pragma unroll
            for (int ng = 0; ng < 4; ng++) {
                uint32_t rb = stg + (uint32_t)((ng * 16 + nB) * FK_ROWB + kt * 32 + kcB * 16);
                uint32_t th[4], tl[4];
                ldsm4(th, rb);
                ldsm4(tl, rb + FK_TILE);
                mma16816(sacc[2 * ng],     qah[kt], th);
                mma16816(sacc[2 * ng],     qah[kt], tl);
                mma16816(sacc[2 * ng],     qal,     th);
                mma16816(sacc[2 * ng + 1], qah[kt], th + 2);
                mma16816(sacc[2 * ng + 1], qah[kt], tl + 2);
                mma16816(sacc[2 * ng + 1], qal,     th + 2);
            }
        }

        // ---- causal mask ----
        if (kb >= 2 * qb) {
            const int kvb = kb * 64 + 2 * t4;
#pragma unroll
            for (int nt = 0; nt < 8; nt++) {
                int c0 = kvb + nt * 8;
                if (c0 > qrow0)     sacc[nt][0] = -1e30f;
                if (c0 + 1 > qrow0) sacc[nt][1] = -1e30f;
                if (c0 > qrow1)     sacc[nt][2] = -1e30f;
                if (c0 + 1 > qrow1) sacc[nt][3] = -1e30f;
            }
        }

        // ---- online softmax ----
        float rm0 = -1e30f, rm1 = -1e30f;
#pragma unroll
        for (int nt = 0; nt < 8; nt++) {
            rm0 = fmaxf(rm0, fmaxf(sacc[nt][0], sacc[nt][1]));
            rm1 = fmaxf(rm1, fmaxf(sacc[nt][2], sacc[nt][3]));
        }
        rm0 = fmaxf(rm0, __shfl_xor_sync(0xffffffffu, rm0, 1));
        rm0 = fmaxf(rm0, __shfl_xor_sync(0xffffffffu, rm0, 2));
        rm1 = fmaxf(rm1, __shfl_xor_sync(0xffffffffu, rm1, 1));
        rm1 = fmaxf(rm1, __shfl_xor_sync(0xffffffffu, rm1, 2));
        float mn0 = fmaxf(m0, rm0), mn1 = fmaxf(m1, rm1);
        float a0 = __expf(m0 - mn0), a1 = __expf(m1 - mn1);
        m0 = mn0; m1 = mn1;
        float rs0 = 0.f, rs1 = 0.f;
#pragma unroll
        for (int nt = 0; nt < 8; nt++) {
            sacc[nt][0] = __expf(sacc[nt][0] - mn0);
            sacc[nt][1] = __expf(sacc[nt][1] - mn0);
            sacc[nt][2] = __expf(sacc[nt][2] - mn1);
            sacc[nt][3] = __expf(sacc[nt][3] - mn1);
            rs0 += sacc[nt][0] + sacc[nt][1];
            rs1 += sacc[nt][2] + sacc[nt][3];
        }
        rs0 += __shfl_xor_sync(0xffffffffu, rs0, 1);
        rs0 += __shfl_xor_sync(0xffffffffu, rs0, 2);
        rs1 += __shfl_xor_sync(0xffffffffu, rs1, 1);
        rs1 += __shfl_xor_sync(0xffffffffu, rs1, 2);
        l0 = l0 * a0 + rs0;
        l1 = l1 * a1 + rs1;
#pragma unroll
        for (int nt = 0; nt < 16; nt++) {
            oacc[nt][0] *= a0; oacc[nt][1] *= a0;
            oacc[nt][2] *= a1; oacc[nt][3] *= a1;
        }

        // ---- PV: P in regs, V via ldmatrix.trans on natural layout ----
        const uint32_t stg_v = stg + 2 * FK_TILE;
#pragma unroll
        for (int kt2 = 0; kt2 < 4; kt2++) {
            uint32_t pah[4], pal[4];
            pah[0] = pack_split(sacc[2 * kt2][0],     sacc[2 * kt2][1],     pal[0]);
            pah[1] = pack_split(sacc[2 * kt2][2],     sacc[2 * kt2][3],     pal[1]);
            pah[2] = pack_split(sacc[2 * kt2 + 1][0], sacc[2 * kt2 + 1][1], pal[2]);
            pah[3] = pack_split(sacc[2 * kt2 + 1][2], sacc[2 * kt2 + 1][3], pal[3]);
            const uint32_t vrow = stg_v + (uint32_t)((kt2 * 16 + rA) * FV_ROWB + kcA * 16);
#pragma unroll
            for (int ng = 0; ng < 8; ng++) {
                uint32_t vh[4], vl[4];
                ldsm4t(vh, vrow + ng * 32);
                ldsm4t(vl, vrow + ng * 32 + FV_TILE);
                mma16816(oacc[2 * ng],     pah, vh);
                mma16816(oacc[2 * ng],     pah, vl);
                mma16816(oacc[2 * ng],     pal, vh);
                mma16816(oacc[2 * ng + 1], pah, vh + 2);
                mma16816(oacc[2 * ng + 1], pah, vl + 2);
                mma16816(oacc[2 * ng + 1], pal, vh + 2);
            }
        }
        __syncthreads();
        if (kb + 2 < nkv) load_kv(kb + 2);
    }

    // ---- epilogue: normalize, split, write [B,S,H*DK] ----
    const float inv0 = 1.f / l0, inv1 = 1.f / l1;
    const size_t base0 = (rowbase + qrow0) * Dd + hoff;
    const size_t base1 = (rowbase + qrow1) * Dd + hoff;
#pragma unroll
    for (int nt = 0; nt < 16; nt++) {
        int col = nt * 8 + 2 * t4;
        uint32_t lw0, lw1;
        uint32_t hw0 = pack_split(oacc[nt][0] * inv0, oacc[nt][1] * inv0, lw0);
        uint32_t hw1 = pack_split(oacc[nt][2] * inv1, oacc[nt][3] * inv1, lw1);
        *(uint32_t*)&ohi[base0 + col] = hw0;
        *(uint32_t*)&olo[base0 + col] = lw0;
        *(uint32_t*)&ohi[base1 + col] = hw1;
        *(uint32_t*)&olo[base1 + col] = lw1;
    }
}

// ---------------------------------------------------------------------------
// Launch
// ---------------------------------------------------------------------------
extern "C" void kernel_launch(void* const* d_in, const int* in_sizes, int n_in,
                              void* d_out, int out_size)
{
    (void)in_sizes; (void)n_in; (void)out_size;
    const float* x    = (const float*)d_in[0];
    const float* Wq   = (const float*)d_in[1];
    const float* Wk   = (const float*)d_in[2];
    const float* Wv   = (const float*)d_in[3];
    const float* Wo   = (const float*)d_in[4];
    const float* cosd = (const float*)d_in[5];
    const float* sind = (const float*)d_in[6];
    float* out = (float*)d_out;

    __nv_bfloat16 *xhi, *xlo, *whi, *wlo;
    __nv_bfloat16 *qsh, *qsl, *ksh, *ksl, *vsh, *vsl;
    cudaGetSymbolAddress((void**)&xhi, g_xhi);
    cudaGetSymbolAddress((void**)&xlo, g_xlo);
    cudaGetSymbolAddress((void**)&whi, g_whi);
    cudaGetSymbolAddress((void**)&wlo, g_wlo);
    cudaGetSymbolAddress((void**)&qsh, g_qsh);
    cudaGetSymbolAddress((void**)&qsl, g_qsl);
    cudaGetSymbolAddress((void**)&ksh, g_ksh);
    cudaGetSymbolAddress((void**)&ksl, g_ksl);
    cudaGetSymbolAddress((void**)&vsh, g_vsh);
    cudaGetSymbolAddress((void**)&vsl, g_vsl);

    cudaFuncSetAttribute(mma_gemm_kernel<0>,
                         cudaFuncAttributeMaxDynamicSharedMemorySize, (int)MT_SMEM);
    cudaFuncSetAttribute(mma_gemm_kernel<1>,
                         cudaFuncAttributeMaxDynamicSharedMemorySize, (int)MT_SMEM);
    cudaFuncSetAttribute(mma_gemm_kernel<2>,
                         cudaFuncAttributeMaxDynamicSharedMemorySize, (int)MT_SMEM);
    cudaFuncSetAttribute(flash_mma_kernel,
                         cudaFuncAttributeMaxDynamicSharedMemorySize, (int)FL2_SMEM);

    const size_t wN = (size_t)Dd * Dd;
    const int   nX = Mm * Dd;
    const int   nW = (int)wN;

    split_kernel<<<nX / 4 / 256, 256>>>(x,  xhi, xlo, nX);
    split_kernel<<<nW / 4 / 256, 256>>>(Wq, whi + 0 * wN, wlo + 0 * wN, nW);
    split_kernel<<<nW / 4 / 256, 256>>>(Wk, whi + 1 * wN, wlo + 1 * wN, nW);
    split_kernel<<<nW / 4 / 256, 256>>>(Wv, whi + 2 * wN, wlo + 2 * wN, nW);
    split_kernel<<<nW / 4 / 256, 256>>>(Wo, whi + 3 * wN, wlo + 3 * wN, nW);

    const float scale = 0.08838834764831845f;   // 1/sqrt(128)
    dim3 tgrid(Dd / 128, Mm / 128);
    // Q: GEMM + RoPE + scale + split
    mma_gemm_kernel<2><<<tgrid, 256, MT_SMEM>>>(
        xhi, xlo, whi + 0 * wN, wlo + 0 * wN,
        nullptr, qsh, qsl, cosd, sind, scale, Mm, Dd, Dd);
    // K: GEMM + RoPE + split
    mma_gemm_kernel<2><<<tgrid, 256, MT_SMEM>>>(
        xhi, xlo, whi + 1 * wN, wlo + 1 * wN,
        nullptr, ksh, ksl, cosd, sind, 1.0f, Mm, Dd, Dd);
    // V: GEMM + split
    mma_gemm_kernel<1><<<tgrid, 256, MT_SMEM>>>(
        xhi, xlo, whi + 2 * wN, wlo + 2 * wN,
        nullptr, vsh, vsl, nullptr, nullptr, 1.0f, Mm, Dd, Dd);

    dim3 fgrid(Ss / 128, Hh, Bb);
    flash_mma_kernel<<<fgrid, 256, FL2_SMEM>>>(qsh, qsl, ksh, ksl, vsh, vsl,
                                               xhi, xlo);

    // Output projection
    mma_gemm_kernel<0><<<tgrid, 256, MT_SMEM>>>(
        xhi, xlo, whi + 3 * wN, wlo + 3 * wN,
        out, nullptr, nullptr, nullptr, nullptr, 1.0f, Mm, Dd, Dd);
}

// round 9
// speedup vs baseline: 2.5812x; 1.0859x over previous
#include <cuda_runtime.h>
#include <cuda_bf16.h>
#include <cstdint>

// Problem constants
constexpr int Bb  = 4;
constexpr int Ss  = 2048;
constexpr int Dd  = 2048;
constexpr int Hh  = 16;
constexpr int DK  = 128;
constexpr int Mm  = Bb * Ss;          // 8192 rows

// ---------------------------------------------------------------------------
// Scratch (static __device__ arrays)
// ---------------------------------------------------------------------------
__device__ __align__(256) __nv_bfloat16 g_xhi[(size_t)Mm * Dd];
__device__ __align__(256) __nv_bfloat16 g_xlo[(size_t)Mm * Dd];
__device__ __align__(256) __nv_bfloat16 g_whi[4][(size_t)Dd * Dd];
__device__ __align__(256) __nv_bfloat16 g_wlo[4][(size_t)Dd * Dd];

// Q/K (roped) and V, split bf16, natural [B,S,H*DK] layout
constexpr size_t FSZ = (size_t)Mm * Dd;
__device__ __align__(256) __nv_bfloat16 g_qsh[FSZ];
__device__ __align__(256) __nv_bfloat16 g_qsl[FSZ];
__device__ __align__(256) __nv_bfloat16 g_ksh[FSZ];
__device__ __align__(256) __nv_bfloat16 g_ksl[FSZ];
__device__ __align__(256) __nv_bfloat16 g_vsh[FSZ];
__device__ __align__(256) __nv_bfloat16 g_vsl[FSZ];

// ---------------------------------------------------------------------------
// Baseline-ISA helpers
// ---------------------------------------------------------------------------
__device__ __forceinline__ uint32_t smem_u32(const void* p) {
    uint32_t a;
    asm("{ .reg .u64 t; cvta.to.shared.u64 t, %1; cvt.u32.u64 %0, t; }"
        : "=r"(a) : "l"(p));
    return a;
}
__device__ __forceinline__ void ldsm4(uint32_t* r, uint32_t addr) {
    asm volatile("ldmatrix.sync.aligned.m8n8.x4.shared.b16 {%0,%1,%2,%3}, [%4];"
                 : "=r"(r[0]), "=r"(r[1]), "=r"(r[2]), "=r"(r[3])
                 : "r"(addr));
}
__device__ __forceinline__ void ldsm4t(uint32_t* r, uint32_t addr) {
    asm volatile("ldmatrix.sync.aligned.m8n8.x4.trans.shared.b16 {%0,%1,%2,%3}, [%4];"
                 : "=r"(r[0]), "=r"(r[1]), "=r"(r[2]), "=r"(r[3])
                 : "r"(addr));
}
__device__ __forceinline__ void mma16816(float* c, const uint32_t* a,
                                         const uint32_t* b) {
    asm volatile(
        "mma.sync.aligned.m16n8k16.row.col.f32.bf16.bf16.f32 "
        "{%0,%1,%2,%3}, {%4,%5,%6,%7}, {%8,%9}, {%0,%1,%2,%3};"
        : "+f"(c[0]), "+f"(c[1]), "+f"(c[2]), "+f"(c[3])
        : "r"(a[0]), "r"(a[1]), "r"(a[2]), "r"(a[3]), "r"(b[0]), "r"(b[1]));
}
#define CP_COMMIT() asm volatile("cp.async.commit_group;" ::: "memory")

__device__ __forceinline__ uint32_t pack_split(float x, float y, uint32_t& lo_out) {
    __nv_bfloat162 h = __floats2bfloat162_rn(x, y);
    float2 hb = __bfloat1622float2(h);
    __nv_bfloat162 l = __floats2bfloat162_rn(x - hb.x, y - hb.y);
    lo_out = *(uint32_t*)&l;
    return *(uint32_t*)&h;
}

// ---------------------------------------------------------------------------
// Split fp32 -> (bf16 hi, bf16 lo)
// ---------------------------------------------------------------------------
__global__ __launch_bounds__(256) void split_kernel(
    const float* __restrict__ in, __nv_bfloat16* __restrict__ hi,
    __nv_bfloat16* __restrict__ lo, int n)
{
    int i = (blockIdx.x * 256 + threadIdx.x) * 4;
    if (i >= n) return;
    float4 v = *(const float4*)&in[i];
    uint32_t l0, l1;
    uint32_t h0 = pack_split(v.x, v.y, l0);
    uint32_t h1 = pack_split(v.z, v.w, l1);
    *(uint2*)&hi[i] = make_uint2(h0, h1);
    *(uint2*)&lo[i] = make_uint2(l0, l1);
}

// ---------------------------------------------------------------------------
// Split-bf16 tensor-core GEMM via mma.sync.
// 2-stage pipeline + 2 CTAs/SM; product-pass MMA ordering (no RAW chains).
//   MODE 0: C fp32   MODE 1: split bf16   MODE 2: RoPE (+scale) then split
// ---------------------------------------------------------------------------
constexpr int MT_ROWB  = 80;
constexpr int MT_TILEB = 128 * MT_ROWB;
constexpr int MT_STAGE = 4 * MT_TILEB;                 // 40960
constexpr size_t MT_SMEM = 2 * (size_t)MT_STAGE;       // 81920

template <int MODE>
__global__ __launch_bounds__(256, 2) void mma_gemm_kernel(
    const __nv_bfloat16* __restrict__ Ahi, const __nv_bfloat16* __restrict__ Alo,
    const __nv_bfloat16* __restrict__ Bhi, const __nv_bfloat16* __restrict__ Blo,
    float* __restrict__ C, __nv_bfloat16* __restrict__ Chi,
    __nv_bfloat16* __restrict__ Clo, const float* __restrict__ cosd,
    const float* __restrict__ sind, float scale, int M, int N, int K)
{
    extern __shared__ __align__(256) char smem[];
    const uint32_t sbase = smem_u32(smem);
    const int tid = threadIdx.x;
    const int wid = tid >> 5;
    const int lid = tid & 31;
    const int m0 = blockIdx.y * 128;
    const int n0 = blockIdx.x * 128;
    const int warp_m = (wid & 1) * 64;
    const int warp_n = (wid >> 1) * 32;

    const __nv_bfloat16* srcs[4] = {
        Ahi + (size_t)m0 * K, Alo + (size_t)m0 * K,
        Bhi + (size_t)n0 * K, Blo + (size_t)n0 * K };

    const int nchunks = K >> 5;

    auto load_stage = [&](int c) {
        const uint32_t stg = sbase + (uint32_t)(c & 1) * MT_STAGE;
        const int k0 = c << 5;
#pragma unroll
        for (int t = 0; t < 4; t++) {
            const __nv_bfloat16* src = srcs[t] + k0;
            const uint32_t sdst = stg + t * MT_TILEB;
#pragma unroll
            for (int i = 0; i < 2; i++) {
                int idx   = tid + i * 256;
                int row   = idx >> 2;
                int chunk = idx & 3;
                uint32_t d = sdst + row * MT_ROWB + chunk * 16;
                const void* g = (const void*)(src + (size_t)row * K + chunk * 8);
                asm volatile("cp.async.cg.shared.global [%0], [%1], 16;"
                             :: "r"(d), "l"(g));
            }
        }
        CP_COMMIT();
    };

    float acc[4][4][4];
#pragma unroll
    for (int mt = 0; mt < 4; mt++)
#pragma unroll
        for (int nt = 0; nt < 4; nt++)
#pragma unroll
            for (int e = 0; e < 4; e++) acc[mt][nt][e] = 0.f;

    load_stage(0);
    load_stage(1);

    const int matA = lid >> 3;
    const int rA   = (lid & 7) + ((matA & 1) << 3);
    const int kcA  = matA >> 1;
    const int nB   = (lid & 7) + ((matA >> 1) << 3);
    const int kcB  = matA & 1;

    for (int c = 0; c < nchunks; c++) {
        if (c + 1 < nchunks) {
            asm volatile("cp.async.wait_group 1;" ::: "memory");
        } else {
            asm volatile("cp.async.wait_group 0;" ::: "memory");
        }
        __syncthreads();

        const uint32_t stg = sbase + (uint32_t)(c & 1) * MT_STAGE;
        const uint32_t Ah = stg;
        const uint32_t Al = stg + MT_TILEB;
        const uint32_t Bh = stg + 2 * MT_TILEB;
        const uint32_t Bl = stg + 3 * MT_TILEB;

#pragma unroll
        for (int ks = 0; ks < 2; ks++) {
            const int kbyte = ks * 32;
            uint32_t ahi[4][4], alo[4][4], bhi[4][2], blo[4][2];
#pragma unroll
            for (int mt = 0; mt < 4; mt++) {
                uint32_t ra = (uint32_t)((warp_m + mt * 16 + rA) * MT_ROWB
                                         + kbyte + kcA * 16);
                ldsm4(ahi[mt], Ah + ra);
                ldsm4(alo[mt], Al + ra);
            }
#pragma unroll
            for (int ntp = 0; ntp < 2; ntp++) {
                uint32_t rb = (uint32_t)((warp_n + ntp * 16 + nB) * MT_ROWB
                                         + kbyte + kcB * 16);
                uint32_t th[4], tl[4];
                ldsm4(th, Bh + rb);
                ldsm4(tl, Bl + rb);
                bhi[ntp * 2][0] = th[0]; bhi[ntp * 2][1] = th[1];
                bhi[ntp * 2 + 1][0] = th[2]; bhi[ntp * 2 + 1][1] = th[3];
                blo[ntp * 2][0] = tl[0]; blo[ntp * 2][1] = tl[1];
                blo[ntp * 2 + 1][0] = tl[2]; blo[ntp * 2 + 1][1] = tl[3];
            }
            // product-pass ordering: consecutive MMAs never share an accumulator
#pragma unroll
            for (int mt = 0; mt < 4; mt++)
#pragma unroll
                for (int nt = 0; nt < 4; nt++)
                    mma16816(acc[mt][nt], ahi[mt], bhi[nt]);
#pragma unroll
            for (int mt = 0; mt < 4; mt++)
#pragma unroll
                for (int nt = 0; nt < 4; nt++)
                    mma16816(acc[mt][nt], ahi[mt], blo[nt]);
#pragma unroll
            for (int mt = 0; mt < 4; mt++)
#pragma unroll
                for (int nt = 0; nt < 4; nt++)
                    mma16816(acc[mt][nt], alo[mt], bhi[nt]);
        }
        __syncthreads();
        if (c + 2 < nchunks) load_stage(c + 2);
    }

    // ---- epilogue ----
#pragma unroll
    for (int mt = 0; mt < 4; mt++) {
        int r = m0 + warp_m + mt * 16 + (lid >> 2);
#pragma unroll
        for (int nt = 0; nt < 4; nt++) {
            int cn = n0 + warp_n + nt * 8 + 2 * (lid & 3);
            if (MODE == 0) {
                *(float2*)&C[(size_t)r * N + cn] =
                    make_float2(acc[mt][nt][0], acc[mt][nt][1]);
                *(float2*)&C[(size_t)(r + 8) * N + cn] =
                    make_float2(acc[mt][nt][2], acc[mt][nt][3]);
            } else if (MODE == 1) {
                uint32_t lw0, lw1;
                uint32_t hw0 = pack_split(acc[mt][nt][0], acc[mt][nt][1], lw0);
                uint32_t hw1 = pack_split(acc[mt][nt][2], acc[mt][nt][3], lw1);
                *(uint32_t*)&Chi[(size_t)r * N + cn]       = hw0;
                *(uint32_t*)&Clo[(size_t)r * N + cn]       = lw0;
                *(uint32_t*)&Chi[(size_t)(r + 8) * N + cn] = hw1;
                *(uint32_t*)&Clo[(size_t)(r + 8) * N + cn] = lw1;
            } else {
                int j  = (cn & (DK - 1)) >> 1;
                int s0_ = r & (Ss - 1);
                int s1_ = (r + 8) & (Ss - 1);
                float c0 = cosd[s0_ * 64 + j], n0_ = sind[s0_ * 64 + j];
                float c1 = cosd[s1_ * 64 + j], n1_ = sind[s1_ * 64 + j];
                float e0 = (acc[mt][nt][0] * c0 - acc[mt][nt][1] * n0_) * scale;
                float o0 = (acc[mt][nt][1] * c0 + acc[mt][nt][0] * n0_) * scale;
                float e1 = (acc[mt][nt][2] * c1 - acc[mt][nt][3] * n1_) * scale;
                float o1 = (acc[mt][nt][3] * c1 + acc[mt][nt][2] * n1_) * scale;
                uint32_t lw0, lw1;
                uint32_t hw0 = pack_split(e0, o0, lw0);
                uint32_t hw1 = pack_split(e1, o1, lw1);
                *(uint32_t*)&Chi[(size_t)r * N + cn]       = hw0;
                *(uint32_t*)&Clo[(size_t)r * N + cn]       = lw0;
                *(uint32_t*)&Chi[(size_t)(r + 8) * N + cn] = hw1;
                *(uint32_t*)&Clo[(size_t)(r + 8) * N + cn] = lw1;
            }
        }
    }
}

// ---------------------------------------------------------------------------
// Flash attention on mma.sync (split-bf16, causal, online softmax).
// Product-pass MMA ordering; heaviest q-blocks scheduled first.
// grid (S/128, H, B); 256 threads; warp w owns q rows 16w..16w+15.
// ---------------------------------------------------------------------------
constexpr int FQ_ROWB = 272;
constexpr int FK_ROWB = 272;
constexpr int FV_ROWB = 272;
constexpr int FQ_TILE = 128 * FQ_ROWB;        // 34816
constexpr int FK_TILE = 64 * FK_ROWB;         // 17408
constexpr int FV_TILE = 64 * FV_ROWB;         // 17408
constexpr int FKV_STAGE = 2 * FK_TILE + 2 * FV_TILE;   // 69632
constexpr int FKV_OFF = 2 * FQ_TILE;          // 69632
constexpr size_t FL2_SMEM = (size_t)FKV_OFF + 2 * FKV_STAGE;   // 208896

__global__ __launch_bounds__(256, 1) void flash_mma_kernel(
    const __nv_bfloat16* __restrict__ qhi_, const __nv_bfloat16* __restrict__ qlo_,
    const __nv_bfloat16* __restrict__ khi_, const __nv_bfloat16* __restrict__ klo_,
    const __nv_bfloat16* __restrict__ vhi_, const __nv_bfloat16* __restrict__ vlo_,
    __nv_bfloat16* __restrict__ ohi, __nv_bfloat16* __restrict__ olo)
{
    extern __shared__ __align__(256) char smem[];
    const uint32_t sbase = smem_u32(smem);
    const int qb  = gridDim.x - 1 - blockIdx.x;   // heavy CTAs first
    const int h   = blockIdx.y;
    const int b   = blockIdx.z;
    const int tid = threadIdx.x;
    const int wid = tid >> 5;
    const int lid = tid & 31;
    const int g   = lid >> 2;
    const int t4  = lid & 3;

    const size_t rowbase = (size_t)b * Ss;
    const size_t hoff    = (size_t)h * DK;

    // Q tiles (hi, lo) -> smem
#pragma unroll
    for (int t = 0; t < 2; t++) {
        const __nv_bfloat16* src = (t ? qlo_ : qhi_);
        const uint32_t sdst = sbase + t * FQ_TILE;
#pragma unroll
        for (int i = 0; i < 8; i++) {
            int idx = tid + i * 256;
            int row = idx >> 4;
            int ch  = idx & 15;
            const void* gp = (const void*)(src
                + (rowbase + qb * 128 + row) * Dd + hoff + ch * 8);
            asm volatile("cp.async.cg.shared.global [%0], [%1], 16;"
                         :: "r"(sdst + row * FQ_ROWB + ch * 16), "l"(gp));
        }
    }
    CP_COMMIT();

    auto load_kv = [&](int kb) {
        const uint32_t stg = sbase + FKV_OFF + (uint32_t)(kb & 1) * FKV_STAGE;
        const int s0 = kb * 64;
#pragma unroll
        for (int t = 0; t < 2; t++) {
            const __nv_bfloat16* src = (t ? klo_ : khi_);
            const uint32_t sdst = stg + t * FK_TILE;
#pragma unroll
            for (int i = 0; i < 4; i++) {
                int idx = tid + i * 256;
                int row = idx >> 4;
                int ch  = idx & 15;
                const void* gp = (const void*)(src
                    + (rowbase + s0 + row) * Dd + hoff + ch * 8);
                asm volatile("cp.async.cg.shared.global [%0], [%1], 16;"
                             :: "r"(sdst + row * FK_ROWB + ch * 16), "l"(gp));
            }
        }
#pragma unroll
        for (int t = 0; t < 2; t++) {
            const __nv_bfloat16* src = (t ? vlo_ : vhi_);
            const uint32_t sdst = stg + 2 * FK_TILE + t * FV_TILE;
#pragma unroll
            for (int i = 0; i < 4; i++) {
                int idx = tid + i * 256;
                int row = idx >> 4;
                int ch  = idx & 15;
                const void* gp = (const void*)(src
                    + (rowbase + s0 + row) * Dd + hoff + ch * 8);
                asm volatile("cp.async.cg.shared.global [%0], [%1], 16;"
                             :: "r"(sdst + row * FV_ROWB + ch * 16), "l"(gp));
            }
        }
        CP_COMMIT();
    };

    const int nkv = 2 * qb + 2;
    load_kv(0);
    load_kv(1);

    asm volatile("cp.async.wait_group 2;" ::: "memory");  // Q done
    __syncthreads();

    const int matA = lid >> 3;
    const int rA   = (lid & 7) + ((matA & 1) << 3);
    const int kcA  = matA >> 1;
    const int nB   = (lid & 7) + ((matA >> 1) << 3);
    const int kcB  = matA & 1;

    // Preload Q-hi A fragments
    uint32_t qah[8][4];
    const uint32_t qrowaddr = sbase + (uint32_t)((wid * 16 + rA) * FQ_ROWB + kcA * 16);
#pragma unroll
    for (int kt = 0; kt < 8; kt++) ldsm4(qah[kt], qrowaddr + kt * 32);

    float oacc[16][4];
#pragma unroll
    for (int nt = 0; nt < 16; nt++)
#pragma unroll
        for (int e = 0; e < 4; e++) oacc[nt][e] = 0.f;
    float m0 = -1e30f, m1 = -1e30f, l0 = 0.f, l1 = 0.f;

    const int qrow0 = qb * 128 + wid * 16 + g;
    const int qrow1 = qrow0 + 8;

    for (int kb = 0; kb < nkv; kb++) {
        if (kb + 1 < nkv) {
            asm volatile("cp.async.wait_group 1;" ::: "memory");
        } else {
            asm volatile("cp.async.wait_group 0;" ::: "memory");
        }
        __syncthreads();
        const uint32_t stg = sbase + FKV_OFF + (uint32_t)(kb & 1) * FKV_STAGE;

        // ---- scores: 16 x 64 per warp, product-pass ordering ----
        float sacc[8][4];
#pragma unroll
        for (int nt = 0; nt < 8; nt++)
#pragma unroll
            for (int e = 0; e < 4; e++) sacc[nt][e] = 0.f;

#pragma unroll
        for (int kt = 0; kt < 8; kt++) {
            uint32_t qal[4];
            ldsm4(qal, qrowaddr + FQ_TILE + kt * 32);
            uint32_t kh[4][4], kl[4][4];
#pragma unroll
            for (int ng = 0; ng < 4; ng++) {
                uint32_t rb = stg + (uint32_t)((ng * 16 + nB) * FK_ROWB + kt * 32 + kcB * 16);
                ldsm4(kh[ng], rb);
                ldsm4(kl[ng], rb + FK_TILE);
            }
#pragma unroll
            for (int ng = 0; ng < 4; ng++) {
                mma16816(sacc[2 * ng],     qah[kt], kh[ng]);
                mma16816(sacc[2 * ng + 1], qah[kt], kh[ng] + 2);
            }
#pragma unroll
            for (int ng = 0; ng < 4; ng++) {
                mma16816(sacc[2 * ng],     qah[kt], kl[ng]);
                mma16816(sacc[2 * ng + 1], qah[kt], kl[ng] + 2);
            }
#pragma unroll
            for (int ng = 0; ng < 4; ng++) {
                mma16816(sacc[2 * ng],     qal, kh[ng]);
                mma16816(sacc[2 * ng + 1], qal, kh[ng] + 2);
            }
        }

        // ---- causal mask ----
        if (kb >= 2 * qb) {
            const int kvb = kb * 64 + 2 * t4;
#pragma unroll
            for (int nt = 0; nt < 8; nt++) {
                int c0 = kvb + nt * 8;
                if (c0 > qrow0)     sacc[nt][0] = -1e30f;
                if (c0 + 1 > qrow0) sacc[nt][1] = -1e30f;
                if (c0 > qrow1)     sacc[nt][2] = -1e30f;
                if (c0 + 1 > qrow1) sacc[nt][3] = -1e30f;
            }
        }

        // ---- online softmax ----
        float rm0 = -1e30f, rm1 = -1e30f;
#pragma unroll
        for (int nt = 0; nt < 8; nt++) {
            rm0 = fmaxf(rm0, fmaxf(sacc[nt][0], sacc[nt][1]));
            rm1 = fmaxf(rm1, fmaxf(sacc[nt][2], sacc[nt][3]));
        }
        rm0 = fmaxf(rm0, __shfl_xor_sync(0xffffffffu, rm0, 1));
        rm0 = fmaxf(rm0, __shfl_xor_sync(0xffffffffu, rm0, 2));
        rm1 = fmaxf(rm1, __shfl_xor_sync(0xffffffffu, rm1, 1));
        rm1 = fmaxf(rm1, __shfl_xor_sync(0xffffffffu, rm1, 2));
        float mn0 = fmaxf(m0, rm0), mn1 = fmaxf(m1, rm1);
        float a0 = __expf(m0 - mn0), a1 = __expf(m1 - mn1);
        m0 = mn0; m1 = mn1;
        float rs0 = 0.f, rs1 = 0.f;
#pragma unroll
        for (int nt = 0; nt < 8; nt++) {
            sacc[nt][0] = __expf(sacc[nt][0] - mn0);
            sacc[nt][1] = __expf(sacc[nt][1] - mn0);
            sacc[nt][2] = __expf(sacc[nt][2] - mn1);
            sacc[nt][3] = __expf(sacc[nt][3] - mn1);
            rs0 += sacc[nt][0] + sacc[nt][1];
            rs1 += sacc[nt][2] + sacc[nt][3];
        }
        rs0 += __shfl_xor_sync(0xffffffffu, rs0, 1);
        rs0 += __shfl_xor_sync(0xffffffffu, rs0, 2);
        rs1 += __shfl_xor_sync(0xffffffffu, rs1, 1);
        rs1 += __shfl_xor_sync(0xffffffffu, rs1, 2);
        l0 = l0 * a0 + rs0;
        l1 = l1 * a1 + rs1;
#pragma unroll
        for (int nt = 0; nt < 16; nt++) {
            oacc[nt][0] *= a0; oacc[nt][1] *= a0;
            oacc[nt][2] *= a1; oacc[nt][3] *= a1;
        }

        // ---- PV: product-pass ordering over ng-pairs ----
        const uint32_t stg_v = stg + 2 * FK_TILE;
#pragma unroll
        for (int kt2 = 0; kt2 < 4; kt2++) {
            uint32_t pah[4], pal[4];
            pah[0] = pack_split(sacc[2 * kt2][0],     sacc[2 * kt2][1],     pal[0]);
            pah[1] = pack_split(sacc[2 * kt2][2],     sacc[2 * kt2][3],     pal[1]);
            pah[2] = pack_split(sacc[2 * kt2 + 1][0], sacc[2 * kt2 + 1][1], pal[2]);
            pah[3] = pack_split(sacc[2 * kt2 + 1][2], sacc[2 * kt2 + 1][3], pal[3]);
            const uint32_t vrow = stg_v + (uint32_t)((kt2 * 16 + rA) * FV_ROWB + kcA * 16);
#pragma unroll
            for (int ngp = 0; ngp < 4; ngp++) {
                uint32_t vh0[4], vh1[4], vl0[4], vl1[4];
                ldsm4t(vh0, vrow + (2 * ngp) * 32);
                ldsm4t(vl0, vrow + (2 * ngp) * 32 + FV_TILE);
                ldsm4t(vh1, vrow + (2 * ngp + 1) * 32);
                ldsm4t(vl1, vrow + (2 * ngp + 1) * 32 + FV_TILE);
                const int o0 = 4 * ngp;
                mma16816(oacc[o0],     pah, vh0);
                mma16816(oacc[o0 + 1], pah, vh0 + 2);
                mma16816(oacc[o0 + 2], pah, vh1);
                mma16816(oacc[o0 + 3], pah, vh1 + 2);
                mma16816(oacc[o0],     pah, vl0);
                mma16816(oacc[o0 + 1], pah, vl0 + 2);
                mma16816(oacc[o0 + 2], pah, vl1);
                mma16816(oacc[o0 + 3], pah, vl1 + 2);
                mma16816(oacc[o0],     pal, vh0);
                mma16816(oacc[o0 + 1], pal, vh0 + 2);
                mma16816(oacc[o0 + 2], pal, vh1);
                mma16816(oacc[o0 + 3], pal, vh1 + 2);
            }
        }
        __syncthreads();
        if (kb + 2 < nkv) load_kv(kb + 2);
    }

    // ---- epilogue: normalize, split, write [B,S,H*DK] ----
    const float inv0 = 1.f / l0, inv1 = 1.f / l1;
    const size_t base0 = (rowbase + qrow0) * Dd + hoff;
    const size_t base1 = (rowbase + qrow1) * Dd + hoff;
#pragma unroll
    for (int nt = 0; nt < 16; nt++) {
        int col = nt * 8 + 2 * t4;
        uint32_t lw0, lw1;
        uint32_t hw0 = pack_split(oacc[nt][0] * inv0, oacc[nt][1] * inv0, lw0);
        uint32_t hw1 = pack_split(oacc[nt][2] * inv1, oacc[nt][3] * inv1, lw1);
        *(uint32_t*)&ohi[base0 + col] = hw0;
        *(uint32_t*)&olo[base0 + col] = lw0;
        *(uint32_t*)&ohi[base1 + col] = hw1;
        *(uint32_t*)&olo[base1 + col] = lw1;
    }
}

// ---------------------------------------------------------------------------
// Launch
// ---------------------------------------------------------------------------
extern "C" void kernel_launch(void* const* d_in, const int* in_sizes, int n_in,
                              void* d_out, int out_size)
{
    (void)in_sizes; (void)n_in; (void)out_size;
    const float* x    = (const float*)d_in[0];
    const float* Wq   = (const float*)d_in[1];
    const float* Wk   = (const float*)d_in[2];
    const float* Wv   = (const float*)d_in[3];
    const float* Wo   = (const float*)d_in[4];
    const float* cosd = (const float*)d_in[5];
    const float* sind = (const float*)d_in[6];
    float* out = (float*)d_out;

    __nv_bfloat16 *xhi, *xlo, *whi, *wlo;
    __nv_bfloat16 *qsh, *qsl, *ksh, *ksl, *vsh, *vsl;
    cudaGetSymbolAddress((void**)&xhi, g_xhi);
    cudaGetSymbolAddress((void**)&xlo, g_xlo);
    cudaGetSymbolAddress((void**)&whi, g_whi);
    cudaGetSymbolAddress((void**)&wlo, g_wlo);
    cudaGetSymbolAddress((void**)&qsh, g_qsh);
    cudaGetSymbolAddress((void**)&qsl, g_qsl);
    cudaGetSymbolAddress((void**)&ksh, g_ksh);
    cudaGetSymbolAddress((void**)&ksl, g_ksl);
    cudaGetSymbolAddress((void**)&vsh, g_vsh);
    cudaGetSymbolAddress((void**)&vsl, g_vsl);

    cudaFuncSetAttribute(mma_gemm_kernel<0>,
                         cudaFuncAttributeMaxDynamicSharedMemorySize, (int)MT_SMEM);
    cudaFuncSetAttribute(mma_gemm_kernel<1>,
                         cudaFuncAttributeMaxDynamicSharedMemorySize, (int)MT_SMEM);
    cudaFuncSetAttribute(mma_gemm_kernel<2>,
                         cudaFuncAttributeMaxDynamicSharedMemorySize, (int)MT_SMEM);
    cudaFuncSetAttribute(flash_mma_kernel,
                         cudaFuncAttributeMaxDynamicSharedMemorySize, (int)FL2_SMEM);

    const size_t wN = (size_t)Dd * Dd;
    const int   nX = Mm * Dd;
    const int   nW = (int)wN;

    split_kernel<<<nX / 4 / 256, 256>>>(x,  xhi, xlo, nX);
    split_kernel<<<nW / 4 / 256, 256>>>(Wq, whi + 0 * wN, wlo + 0 * wN, nW);
    split_kernel<<<nW / 4 / 256, 256>>>(Wk, whi + 1 * wN, wlo + 1 * wN, nW);
    split_kernel<<<nW / 4 / 256, 256>>>(Wv, whi + 2 * wN, wlo + 2 * wN, nW);
    split_kernel<<<nW / 4 / 256, 256>>>(Wo, whi + 3 * wN, wlo + 3 * wN, nW);

    const float scale = 0.08838834764831845f;   // 1/sqrt(128)
    dim3 tgrid(Dd / 128, Mm / 128);
    // Q: GEMM + RoPE + scale + split
    mma_gemm_kernel<2><<<tgrid, 256, MT_SMEM>>>(
        xhi, xlo, whi + 0 * wN, wlo + 0 * wN,
        nullptr, qsh, qsl, cosd, sind, scale, Mm, Dd, Dd);
    // K: GEMM + RoPE + split
    mma_gemm_kernel<2><<<tgrid, 256, MT_SMEM>>>(
        xhi, xlo, whi + 1 * wN, wlo + 1 * wN,
        nullptr, ksh, ksl, cosd, sind, 1.0f, Mm, Dd, Dd);
    // V: GEMM + split
    mma_gemm_kernel<1><<<tgrid, 256, MT_SMEM>>>(
        xhi, xlo, whi + 2 * wN, wlo + 2 * wN,
        nullptr, vsh, vsl, nullptr, nullptr, 1.0f, Mm, Dd, Dd);

    dim3 fgrid(Ss / 128, Hh, Bb);
    flash_mma_kernel<<<fgrid, 256, FL2_SMEM>>>(qsh, qsl, ksh, ksl, vsh, vsl,
                                               xhi, xlo);

    // Output projection
    mma_gemm_kernel<0><<<tgrid, 256, MT_SMEM>>>(
        xhi, xlo, whi + 3 * wN, wlo + 3 * wN,
        out, nullptr, nullptr, nullptr, nullptr, 1.0f, Mm, Dd, Dd);
}